// round 13
// baseline (speedup 1.0000x reference)
#include <cuda_runtime.h>
#include <cuda_fp16.h>
#include <cstdint>
#include <math_constants.h>

#define EPS 1e-5f
#define HB 64
#define BATCH 128
#define CIN 2048
#define CMID 512
#define HW 196
#define HWP 256
#define KXT 224     // xxt effective K (>=196, /32)
#define K33 4608
#define NFLAT 25088   // 128*196 = 196 tiles of 128 exactly

// ---------------- scratch (static device globals; zero-init at load) --------
__device__ __half g_x_h [(size_t)BATCH * CMID * HWP];  // pad cols stay 0
__device__ __half g_x_l [(size_t)BATCH * CMID * HWP];
__device__ __half g_xT_h[(size_t)BATCH * HW * CMID];
__device__ float  g_att [(size_t)BATCH * CMID * CMID];
__device__ __half g_att_h[(size_t)BATCH * CMID * CMID];
__device__ __half g_yT_h[(size_t)BATCH * HW * CMID];
__device__ __half g_w1_h[(size_t)CMID * CIN];
__device__ __half g_w1_l[(size_t)CMID * CIN];
__device__ __half g_w3_h[(size_t)CMID * K33];   // reordered k = rs*512 + c
__device__ float g_zsum[BATCH * CMID];
__device__ float g_h[BATCH * 200];
__device__ float g_scale1[CMID], g_shift1[CMID], g_scale3[CMID], g_shift3[CMID];

// ---------------- ptx helpers (all non-'a' gated: sm_80-level) --------------
__device__ __forceinline__ uint32_t smem_u32(const void* p) {
    uint32_t a;
    asm("{ .reg .u64 t; cvta.to.shared.u64 t, %1; cvt.u32.u64 %0, t; }"
        : "=r"(a) : "l"(p));
    return a;
}
__device__ __forceinline__ void cp16(uint32_t dst, const void* src) {
    asm volatile("cp.async.ca.shared.global [%0], [%1], 16;"
                 :: "r"(dst), "l"(src));
}
__device__ __forceinline__ void cp16z(uint32_t dst, const void* src, int ok) {
    int sz = ok ? 16 : 0;
    asm volatile("cp.async.ca.shared.global [%0], [%1], 16, %2;"
                 :: "r"(dst), "l"(src), "r"(sz));
}
__device__ __forceinline__ void cp_commit() {
    asm volatile("cp.async.commit_group;" ::: "memory");
}
template<int N> __device__ __forceinline__ void cp_wait() {
    asm volatile("cp.async.wait_group %0;" :: "n"(N) : "memory");
}
__device__ __forceinline__ void ldm4(uint32_t* r, uint32_t addr) {
    asm volatile("ldmatrix.sync.aligned.m8n8.x4.shared.b16 {%0,%1,%2,%3}, [%4];"
                 : "=r"(r[0]), "=r"(r[1]), "=r"(r[2]), "=r"(r[3]) : "r"(addr));
}
__device__ __forceinline__ void ldm2(uint32_t* r, uint32_t addr) {
    asm volatile("ldmatrix.sync.aligned.m8n8.x2.shared.b16 {%0,%1}, [%2];"
                 : "=r"(r[0]), "=r"(r[1]) : "r"(addr));
}
__device__ __forceinline__ void ldm2t(uint32_t* r, uint32_t addr) {
    asm volatile("ldmatrix.sync.aligned.m8n8.x2.trans.shared.b16 {%0,%1}, [%2];"
                 : "=r"(r[0]), "=r"(r[1]) : "r"(addr));
}
__device__ __forceinline__ void sts128(uint32_t a, int4 v) {
    asm volatile("st.shared.v4.b32 [%0], {%1,%2,%3,%4};"
                 :: "r"(a), "r"(v.x), "r"(v.y), "r"(v.z), "r"(v.w));
}
__device__ __forceinline__ void mma16816(float* c, const uint32_t* a,
                                         const uint32_t* b) {
    asm volatile(
        "mma.sync.aligned.m16n8k16.row.col.f32.f16.f16.f32 "
        "{%0,%1,%2,%3}, {%4,%5,%6,%7}, {%8,%9}, {%0,%1,%2,%3};"
        : "+f"(c[0]), "+f"(c[1]), "+f"(c[2]), "+f"(c[3])
        : "r"(a[0]), "r"(a[1]), "r"(a[2]), "r"(a[3]), "r"(b[0]), "r"(b[1]));
}
__device__ __forceinline__ void split_fp16(float v, __half& hi, __half& lo) {
    hi = __float2half_rn(v);
    lo = __float2half_rn(v - __half2float(hi));
}

// ---------------- SMEM geometry ---------------------------------------------
#define TROW 80
#define TILE_B (128 * TROW)          // 10240 B (K-major 128x32 tile)
#define STAGE_B (4 * TILE_B)         // xxt: Ah, Al, Bh, Bl
#define STAGE2_B (2 * TILE_B)        // ygemm/conv: Ah, Bh
#define DYN_SMEM (2 * STAGE_B)       // 81920 B
#define DYN2_SMEM (2 * STAGE2_B)     // 40960 B (ygemm)
#define DYNC_SMEM (3 * STAGE2_B)     // 61440 B (conv, 3-stage)
// reduce: W tiles K-major (TROW), F tiles N-major 32k x 128n, 272 B rows
#define FROWB 272
#define FTILE_B (32 * FROWB)         // 8704 B
#define RFOFF_H (2 * TILE_B)         // 20480
#define RFOFF_L (RFOFF_H + FTILE_B)  // 29184
#define RSTAGE_B (2 * TILE_B + 2 * FTILE_B)  // 37888
#define RDYN_SMEM (2 * RSTAGE_B)     // 75776

// contiguous 128x32 K-major tile load via cp.async
__device__ __forceinline__ void cpa_tile(uint32_t sdst, const __half* g,
                                         size_t stride, int k0, int tid) {
    #pragma unroll
    for (int it = 0; it < 2; it++) {
        int ch = it * 256 + tid;
        int row = ch >> 2, seg = ch & 3;
        cp16(sdst + row * TROW + seg * 16,
             g + (size_t)row * stride + k0 + seg * 8);
    }
}
__device__ __forceinline__ void cpa_tile_clamp(uint32_t sdst, const __half* g,
                                               size_t stride, int row0,
                                               int maxrow, int k0, int tid) {
    #pragma unroll
    for (int it = 0; it < 2; it++) {
        int ch = it * 256 + tid;
        int row = ch >> 2, seg = ch & 3;
        int rg = row0 + row; if (rg > maxrow) rg = maxrow;
        cp16(sdst + row * TROW + seg * 16,
             g + (size_t)rg * stride + k0 + seg * 8);
    }
}

// one k16 slab, K-major B (ldm2): 4x4 atoms of m16n8k16
__device__ __forceinline__ void mma_k16(uint32_t aBase, uint32_t bBase, int kk,
                                        int lane, float c[4][4][4]) {
    uint32_t a[4][4], b[4][2];
    int arow = lane & 15, asel = lane >> 4;
    #pragma unroll
    for (int am = 0; am < 4; am++)
        ldm4(a[am], aBase + (am * 16 + arow) * TROW + (kk + asel * 8) * 2);
    int brow = lane & 7, bsel = (lane >> 3) & 1;
    #pragma unroll
    for (int bn = 0; bn < 4; bn++)
        ldm2(b[bn], bBase + (bn * 8 + brow) * TROW + (kk + bsel * 8) * 2);
    #pragma unroll
    for (int am = 0; am < 4; am++)
        #pragma unroll
        for (int bn = 0; bn < 4; bn++)
            mma16816(c[am][bn], a[am], b[bn]);
}
// one k16 slab, N-major B (ldm2t): fBase already includes wn*2
__device__ __forceinline__ void mma_k16_t(uint32_t aBase, uint32_t fBase, int kk,
                                          int lane, float c[4][4][4]) {
    uint32_t a[4][4], b[4][2];
    int arow = lane & 15, asel = lane >> 4;
    #pragma unroll
    for (int am = 0; am < 4; am++)
        ldm4(a[am], aBase + (am * 16 + arow) * TROW + (kk + asel * 8) * 2);
    uint32_t frow = fBase + (kk + (lane & 15)) * FROWB;
    #pragma unroll
    for (int bn = 0; bn < 4; bn++)
        ldm2t(b[bn], frow + bn * 16);
    #pragma unroll
    for (int am = 0; am < 4; am++)
        #pragma unroll
        for (int bn = 0; bn < 4; bn++)
            mma16816(c[am][bn], a[am], b[bn]);
}

// 3-term stages
__device__ __forceinline__ void stage_xxt(uint32_t sb, int wm, int wn,
                                          int lane, float c[4][4][4]) {
    uint32_t Ah = sb + wm * TROW,              Al = Ah + TILE_B;
    uint32_t Bh = sb + 2 * TILE_B + wn * TROW, Bl = Bh + TILE_B;
    #pragma unroll
    for (int kk = 0; kk < 32; kk += 16) {
        mma_k16(Ah, Bh, kk, lane, c);
        mma_k16(Ah, Bl, kk, lane, c);
        mma_k16(Al, Bh, kk, lane, c);
    }
}
__device__ __forceinline__ void stage_reduce(uint32_t sb, int wm, int wn,
                                             int lane, float c[4][4][4]) {
    uint32_t Ah = sb + wm * TROW, Al = Ah + TILE_B;
    uint32_t Fh = sb + RFOFF_H + wn * 2, Fl = sb + RFOFF_L + wn * 2;
    #pragma unroll
    for (int kk = 0; kk < 32; kk += 16) {
        mma_k16_t(Ah, Fh, kk, lane, c);
        mma_k16_t(Ah, Fl, kk, lane, c);
        mma_k16_t(Al, Fh, kk, lane, c);
    }
}
// 1-term stage (ygemm/conv)
__device__ __forceinline__ void stage_compute_1(uint32_t sb, int wm, int wn,
                                                int lane, float c[4][4][4]) {
    uint32_t Ah = sb + wm * TROW;
    uint32_t Bh = sb + TILE_B + wn * TROW;
    #pragma unroll
    for (int kk = 0; kk < 32; kk += 16) mma_k16(Ah, Bh, kk, lane, c);
}

#define GEMM_VARS()                                                            \
    extern __shared__ __align__(16) char dsm[];                                \
    uint32_t sb0 = smem_u32(dsm);                                              \
    int tid = threadIdx.x, wid = tid >> 5, lane = tid & 31;                    \
    int wm = (wid >> 2) * 64, wn = (wid & 3) * 32;                             \
    float c[4][4][4] = {};

// ---------------- small prep kernels ----------------------------------------
__global__ void k_zero() {
    g_zsum[blockIdx.x * blockDim.x + threadIdx.x] = 0.f;
}
__global__ void prep_bn(const float* __restrict__ rb, const float* __restrict__ rg,
                        const float* __restrict__ rbe, const float* __restrict__ rm,
                        const float* __restrict__ rv,
                        const float* __restrict__ cb, const float* __restrict__ cg,
                        const float* __restrict__ cbe, const float* __restrict__ cm,
                        const float* __restrict__ cv) {
    int i = blockIdx.x * blockDim.x + threadIdx.x;
    if (i < CMID) {
        float inv = rg[i] * rsqrtf(rv[i] + EPS);
        g_scale1[i] = inv;
        g_shift1[i] = (rb[i] - rm[i]) * inv + rbe[i];
        float inv3 = cg[i] * rsqrtf(cv[i] + EPS);
        g_scale3[i] = inv3;
        g_shift3[i] = (cb[i] - cm[i]) * inv3 + cbe[i];
    }
}
__global__ void cvt_w1(const float* __restrict__ w) {
    int i = blockIdx.x * blockDim.x + threadIdx.x;
    __half hi, lo; split_fp16(w[i], hi, lo);
    g_w1_h[i] = hi; g_w1_l[i] = lo;
}
__global__ void cvt_w3(const float* __restrict__ w) {
    int i = blockIdx.x * blockDim.x + threadIdx.x;   // over 512*4608
    int o = i / K33, k = i - o * K33;
    int rs = k >> 9, cc = k & 511;
    int r = rs / 3, s = rs - r * 3;
    g_w3_h[i] = __float2half_rn(w[((o * CMID + cc) * 3 + r) * 3 + s]);
}

// ---------------- K1: reduce GEMM (M=512, N=25088, K=2048) + BN/ReLU --------
// B loaded straight from fp32 features (coalesced along hw), split in-kernel.
__global__ __launch_bounds__(256, 2) void k_reduce_mma(const float* __restrict__ f2,
                                                       const float* __restrict__ f3) {
    GEMM_VARS();
    int m0 = blockIdx.x * 128, n0 = blockIdx.y * 128;
    const int T = CIN / 32;    // 64 stages
    const __half* Awh = g_w1_h + (size_t)m0 * CIN;
    const __half* Awl = g_w1_l + (size_t)m0 * CIN;
    // F geometry: tile cols n0..n0+127 span at most 2 batches
    int b0 = n0 / HW;
    int bp = (b0 + 1) * HW;                 // global n where batch increments
    int b1 = (b0 + 1 < BATCH) ? b0 + 1 : BATCH - 1;
    const float* F0 = (b0 < HB) ? f2 + (size_t)b0 * CIN * HW
                                : f3 + (size_t)(b0 - HB) * CIN * HW;
    const float* F1 = (b1 < HB) ? f2 + (size_t)b1 * CIN * HW
                                : f3 + (size_t)(b1 - HB) * CIN * HW;
    int h0 = b0 * HW, h1 = b1 * HW;
    int fk = tid >> 3;                      // k row 0..31
    int fng = n0 + (tid & 7) * 16;          // global n start (16 elems)
    uint32_t fcol = (uint32_t)(tid & 7) * 32u;  // local byte col in F tile

    float fr[16];
    #define LDF(kt) {                                                          \
        const float* r0 = F0 + (size_t)((kt) * 32 + fk) * HW;                  \
        const float* r1 = F1 + (size_t)((kt) * 32 + fk) * HW;                  \
        _Pragma("unroll")                                                      \
        for (int e = 0; e < 16; e++) {                                         \
            int n = fng + e;                                                   \
            const float* p = (n < bp) ? r0 + (n - h0) : r1 + (n - h1);         \
            fr[e] = *p;                                                        \
        } }
    #define STSF(s) {                                                          \
        uint32_t ph[8], pl[8];                                                 \
        _Pragma("unroll")                                                      \
        for (int e = 0; e < 8; e++) {                                          \
            __half h0_, l0_, h1_, l1_;                                         \
            split_fp16(fr[2 * e], h0_, l0_);                                   \
            split_fp16(fr[2 * e + 1], h1_, l1_);                               \
            __half2 hh = __halves2half2(h0_, h1_);                             \
            __half2 ll = __halves2half2(l0_, l1_);                             \
            ph[e] = *reinterpret_cast<uint32_t*>(&hh);                         \
            pl[e] = *reinterpret_cast<uint32_t*>(&ll);                         \
        }                                                                      \
        uint32_t fa = (s) + RFOFF_H + (uint32_t)fk * FROWB + fcol;             \
        sts128(fa,      make_int4(ph[0], ph[1], ph[2], ph[3]));                \
        sts128(fa + 16, make_int4(ph[4], ph[5], ph[6], ph[7]));                \
        fa += (RFOFF_L - RFOFF_H);                                             \
        sts128(fa,      make_int4(pl[0], pl[1], pl[2], pl[3]));                \
        sts128(fa + 16, make_int4(pl[4], pl[5], pl[6], pl[7]));                \
    }
    #define ISSUEW(kt) {                                                       \
        uint32_t s = sb0 + ((kt) & 1) * RSTAGE_B; int k0 = (kt) * 32;          \
        cpa_tile(s,          Awh, CIN, k0, tid);                               \
        cpa_tile(s + TILE_B, Awl, CIN, k0, tid);                               \
        cp_commit(); }

    LDF(0);
    ISSUEW(0);
    for (int kt = 0; kt < T; kt++) {
        uint32_t s = sb0 + (kt & 1) * RSTAGE_B;
        STSF(s);
        if (kt + 1 < T) LDF(kt + 1);
        cp_wait<0>();
        __syncthreads();
        if (kt + 1 < T) ISSUEW(kt + 1);
        stage_reduce(s, wm, wn, lane, c);
        __syncthreads();
    }
    #undef LDF
    #undef STSF
    #undef ISSUEW
    #pragma unroll
    for (int am = 0; am < 4; am++) {
        #pragma unroll
        for (int half = 0; half < 2; half++) {
            int o = m0 + wm + am * 16 + (lane >> 2) + half * 8;
            float sc = g_scale1[o], sh = g_shift1[o];
            #pragma unroll
            for (int bn = 0; bn < 4; bn++) {
                #pragma unroll
                for (int e = 0; e < 2; e++) {
                    float v = c[am][bn][half * 2 + e];
                    v = fmaxf(v * sc + sh, 0.f);
                    int col = n0 + wn + bn * 8 + 2 * (lane & 3) + e;
                    int b = col / HW, hw = col - b * HW;
                    __half hi, lo; split_fp16(v, hi, lo);
                    size_t i1 = ((size_t)b * CMID + o) * HWP + hw;
                    g_x_h[i1] = hi; g_x_l[i1] = lo;
                    g_xT_h[((size_t)b * HW + hw) * CMID + o] = hi;
                }
            }
        }
    }
}

// ---------------- K2: XXt per batch (M=N=512, K=196 pad 224) ----------------
__global__ __launch_bounds__(256, 2) void k_xxt_mma() {
    GEMM_VARS();
    int n0 = blockIdx.x * 128, m0 = blockIdx.y * 128, b = blockIdx.z;
    const __half* Xh = g_x_h + (size_t)b * CMID * HWP;
    const __half* Xl = g_x_l + (size_t)b * CMID * HWP;
    const int T = KXT / 32;    // 7 stages
    #define ISSUE(kt) {                                                        \
        uint32_t s = sb0 + ((kt) & 1) * STAGE_B; int k0 = (kt) * 32;           \
        cpa_tile(s,              Xh + (size_t)m0 * HWP, HWP, k0, tid);         \
        cpa_tile(s + TILE_B,     Xl + (size_t)m0 * HWP, HWP, k0, tid);         \
        cpa_tile(s + 2 * TILE_B, Xh + (size_t)n0 * HWP, HWP, k0, tid);         \
        cpa_tile(s + 3 * TILE_B, Xl + (size_t)n0 * HWP, HWP, k0, tid);         \
        cp_commit(); }
    ISSUE(0);
    for (int kt = 0; kt < T; kt++) {
        cp_wait<0>();
        __syncthreads();
        if (kt + 1 < T) ISSUE(kt + 1);
        stage_xxt(sb0 + (kt & 1) * STAGE_B, wm, wn, lane, c);
        __syncthreads();
    }
    #undef ISSUE
    float* out = g_att + (size_t)b * CMID * CMID;
    #pragma unroll
    for (int am = 0; am < 4; am++)
        #pragma unroll
        for (int half = 0; half < 2; half++) {
            int r = m0 + wm + am * 16 + (lane >> 2) + half * 8;
            #pragma unroll
            for (int bn = 0; bn < 4; bn++) {
                int col = n0 + wn + bn * 8 + 2 * (lane & 3);
                out[(size_t)r * CMID + col]     = c[am][bn][half * 2 + 0];
                out[(size_t)r * CMID + col + 1] = c[am][bn][half * 2 + 1];
            }
        }
}

// ---------------- K3: softmax(-S) rowwise -> fp16 (single) ------------------
__global__ __launch_bounds__(256) void k_softmax() {
    int gw = (blockIdx.x * blockDim.x + threadIdx.x) >> 5;
    int lane = threadIdx.x & 31;
    if (gw >= BATCH * CMID) return;
    const float* row = g_att + (size_t)gw * CMID;
    float mn = CUDART_INF_F;
    #pragma unroll
    for (int t = 0; t < 16; t++) mn = fminf(mn, row[lane + t * 32]);
    #pragma unroll
    for (int o = 16; o; o >>= 1) mn = fminf(mn, __shfl_xor_sync(~0u, mn, o));
    float e[16], sum = 0.f;
    #pragma unroll
    for (int t = 0; t < 16; t++) { e[t] = __expf(mn - row[lane + t * 32]); sum += e[t]; }
    #pragma unroll
    for (int o = 16; o; o >>= 1) sum += __shfl_xor_sync(~0u, sum, o);
    float inv = 1.f / sum;
    #pragma unroll
    for (int t = 0; t < 16; t++)
        g_att_h[(size_t)gw * CMID + lane + t * 32] = __float2half_rn(e[t] * inv);
}

// ---------------- K4: y = att @ X (M=512, N=196pad256, K=512), 1-term -------
__global__ __launch_bounds__(256, 2) void k_ygemm_mma() {
    GEMM_VARS();
    int n0 = blockIdx.x * 128, m0 = blockIdx.y * 128, b = blockIdx.z;
    const __half* Ah = g_att_h + ((size_t)b * CMID + m0) * CMID;
    const __half* Bh = g_xT_h + (size_t)b * HW * CMID;
    const int T = CMID / 32;   // 16 stages
    #define ISSUE(kt) {                                                        \
        uint32_t s = sb0 + ((kt) & 1) * STAGE2_B; int k0 = (kt) * 32;          \
        cpa_tile(s, Ah, CMID, k0, tid);                                        \
        cpa_tile_clamp(s + TILE_B, Bh, CMID, n0, HW - 1, k0, tid);             \
        cp_commit(); }
    ISSUE(0);
    for (int kt = 0; kt < T; kt++) {
        cp_wait<0>();
        __syncthreads();
        if (kt + 1 < T) ISSUE(kt + 1);
        stage_compute_1(sb0 + (kt & 1) * STAGE2_B, wm, wn, lane, c);
        __syncthreads();
    }
    #undef ISSUE
    #pragma unroll
    for (int am = 0; am < 4; am++)
        #pragma unroll
        for (int half = 0; half < 2; half++) {
            int i = m0 + wm + am * 16 + (lane >> 2) + half * 8;
            #pragma unroll
            for (int bn = 0; bn < 4; bn++)
                #pragma unroll
                for (int e = 0; e < 2; e++) {
                    int col = n0 + wn + bn * 8 + 2 * (lane & 3) + e;
                    if (col < HW)
                        g_yT_h[((size_t)b * HW + col) * CMID + i] =
                            __float2half_rn(c[am][bn][half * 2 + e]);
                }
        }
}

// ---------------- K5: conv3 implicit GEMM (M=512, N=25088, K=4608), 1-term --
// grid (4 m, 196 n). 3-buffer, 2-deep pipeline, single sync per stage.
__global__ __launch_bounds__(256, 2) void k_conv_mma() {
    GEMM_VARS();
    int m0 = blockIdx.x * 128, n0 = blockIdx.y * 128;
    const int T = K33 / 32;    // 144 stages
    int gr[2], gb[2], gph[2], gpw[2];
    #pragma unroll
    for (int it = 0; it < 2; it++) {
        int row = it * 64 + (tid >> 2);
        gr[it] = row;
        int col = n0 + row;
        gb[it] = col / HW;
        int p = col - gb[it] * HW;
        gph[it] = p / 14; gpw[it] = p - gph[it] * 14;
    }
    int seg = tid & 3;
    #define ISSUE(kt) {                                                        \
        uint32_t s = sb0 + ((kt) % 3) * STAGE2_B; int k0 = (kt) * 32;          \
        cpa_tile(s, g_w3_h + (size_t)m0 * K33, K33, k0, tid);                  \
        int rs = (kt) >> 4, c0 = ((kt) & 15) * 32;                             \
        int dr = rs / 3 - 1, ds = rs - (rs / 3) * 3 - 1;                       \
        _Pragma("unroll")                                                      \
        for (int it = 0; it < 2; it++) {                                       \
            int ih = gph[it] + dr, iw = gpw[it] + ds;                          \
            int ok = ((unsigned)ih < 14u) && ((unsigned)iw < 14u);             \
            size_t pix = (size_t)gb[it] * HW + (ok ? ih * 14 + iw : 0);        \
            size_t gidx = pix * CMID + c0 + seg * 8;                           \
            cp16z(s + TILE_B + gr[it] * TROW + seg * 16, g_yT_h + gidx, ok);   \
        }                                                                      \
        cp_commit(); }
    ISSUE(0);
    ISSUE(1);
    for (int kt = 0; kt < T; kt++) {
        if (kt + 1 < T) cp_wait<1>(); else cp_wait<0>();
        __syncthreads();
        if (kt + 2 < T) ISSUE(kt + 2);
        stage_compute_1(sb0 + (kt % 3) * STAGE2_B, wm, wn, lane, c);
        __syncthreads();
    }
    #undef ISSUE
    // fused BN + ReLU + GAP
    int b0 = n0 / HW;
    int split = (b0 + 1) * HW - n0;   // local cols < split belong to b0
    #pragma unroll
    for (int am = 0; am < 4; am++)
        #pragma unroll
        for (int half = 0; half < 2; half++) {
            int o = m0 + wm + am * 16 + (lane >> 2) + half * 8;
            float sc = g_scale3[o], sh = g_shift3[o];
            float s0 = 0.f, s1 = 0.f;
            #pragma unroll
            for (int bn = 0; bn < 4; bn++)
                #pragma unroll
                for (int e = 0; e < 2; e++) {
                    float v = fmaxf(c[am][bn][half * 2 + e] * sc + sh, 0.f);
                    int lcol = wn + bn * 8 + 2 * (lane & 3) + e;
                    if (lcol < split) s0 += v; else s1 += v;
                }
            s0 += __shfl_xor_sync(~0u, s0, 1);
            s0 += __shfl_xor_sync(~0u, s0, 2);
            s1 += __shfl_xor_sync(~0u, s1, 1);
            s1 += __shfl_xor_sync(~0u, s1, 2);
            if ((lane & 3) == 0) {
                atomicAdd(&g_zsum[b0 * CMID + o], s0 * (1.f / HW));
                if (split < 128)
                    atomicAdd(&g_zsum[(b0 + 1) * CMID + o], s1 * (1.f / HW));
            }
        }
}

// ---------------- K7: fc1 + ReLU --------------------------------------------
__global__ __launch_bounds__(256) void k_fc1(const float* __restrict__ w,
                                             const float* __restrict__ bias) {
    int gw = (blockIdx.x * blockDim.x + threadIdx.x) >> 5;
    int lane = threadIdx.x & 31;
    if (gw >= BATCH * 200) return;
    int b = gw / 200, j = gw - b * 200;
    const float* zr = g_zsum + b * CMID;
    const float* wr = w + (size_t)j * CMID;
    float s = 0.f;
    for (int k = lane; k < CMID; k += 32) s += zr[k] * wr[k];
    #pragma unroll
    for (int o = 16; o; o >>= 1) s += __shfl_xor_sync(~0u, s, o);
    if (lane == 0) g_h[gw] = fmaxf(s + bias[j], 0.f);
}

// ---------------- K8: fc2 + branch-sum --------------------------------------
__global__ __launch_bounds__(256) void k_fc2(const float* __restrict__ w,
                                             const float* __restrict__ bias,
                                             float* __restrict__ out) {
    int gw = (blockIdx.x * blockDim.x + threadIdx.x) >> 5;
    int lane = threadIdx.x & 31;
    if (gw >= HB * 200) return;
    int b = gw / 200, j = gw - b * 200;
    const float* h1 = g_h + (size_t)b * 200;
    const float* h2 = g_h + (size_t)(b + HB) * 200;
    const float* wr = w + (size_t)j * 200;
    float s = 0.f;
    for (int k = lane; k < 200; k += 32) s += (h1[k] + h2[k]) * wr[k];
    #pragma unroll
    for (int o = 16; o; o >>= 1) s += __shfl_xor_sync(~0u, s, o);
    if (lane == 0) out[gw] = s + 2.f * bias[j];
}

// ---------------- launch ----------------------------------------------------
extern "C" void kernel_launch(void* const* d_in, const int* in_sizes, int n_in,
                              void* d_out, int out_size) {
    const float* f2  = (const float*)d_in[0];
    const float* f3  = (const float*)d_in[1];
    const float* rw  = (const float*)d_in[2];
    const float* rb  = (const float*)d_in[3];
    const float* rg  = (const float*)d_in[4];
    const float* rbe = (const float*)d_in[5];
    const float* rm  = (const float*)d_in[6];
    const float* rv  = (const float*)d_in[7];
    const float* c3w = (const float*)d_in[8];
    const float* c3b = (const float*)d_in[9];
    const float* c3g = (const float*)d_in[10];
    const float* c3be= (const float*)d_in[11];
    const float* c3m = (const float*)d_in[12];
    const float* c3v = (const float*)d_in[13];
    const float* f1w = (const float*)d_in[14];
    const float* f1b = (const float*)d_in[15];
    const float* f2w = (const float*)d_in[16];
    const float* f2b = (const float*)d_in[17];
    float* out = (float*)d_out;

    cudaFuncSetAttribute(k_reduce_mma, cudaFuncAttributeMaxDynamicSharedMemorySize, RDYN_SMEM);
    cudaFuncSetAttribute(k_xxt_mma,    cudaFuncAttributeMaxDynamicSharedMemorySize, DYN_SMEM);
    cudaFuncSetAttribute(k_ygemm_mma,  cudaFuncAttributeMaxDynamicSharedMemorySize, DYN2_SMEM);
    cudaFuncSetAttribute(k_conv_mma,   cudaFuncAttributeMaxDynamicSharedMemorySize, DYNC_SMEM);

    k_zero<<<BATCH * CMID / 256, 256>>>();
    prep_bn<<<2, 256>>>(rb, rg, rbe, rm, rv, c3b, c3g, c3be, c3m, c3v);
    cvt_w1<<<(CMID * CIN) / 256, 256>>>(rw);
    cvt_w3<<<(CMID * K33) / 256, 256>>>(c3w);

    k_reduce_mma<<<dim3(4, NFLAT / 128), 256, RDYN_SMEM>>>(f2, f3);
    k_xxt_mma<<<dim3(4, 4, BATCH), 256, DYN_SMEM>>>();
    k_softmax<<<(BATCH * CMID) / 8, 256>>>();
    k_ygemm_mma<<<dim3(2, 4, BATCH), 256, DYN2_SMEM>>>();
    k_conv_mma<<<dim3(4, NFLAT / 128), 256, DYNC_SMEM>>>();
    k_fc1<<<(BATCH * 200 + 7) / 8, 256>>>(f1w, f1b);
    k_fc2<<<(HB * 200 + 7) / 8, 256>>>(f2w, f2b, out);
}

// round 14
// speedup vs baseline: 1.0845x; 1.0845x over previous
#include <cuda_runtime.h>
#include <cuda_fp16.h>
#include <cstdint>
#include <math_constants.h>

#define EPS 1e-5f
#define HB 64
#define BATCH 128
#define CIN 2048
#define CMID 512
#define HW 196
#define HWP 256
#define KXT 224     // xxt effective K (>=196, /32)
#define K33 4608
#define NFLAT 25088   // 128*196 = 196 tiles of 128 exactly

// ---------------- scratch (static device globals; zero-init at load) --------
__device__ __half g_fT_h[(size_t)NFLAT * CIN];
__device__ __half g_fT_l[(size_t)NFLAT * CIN];
__device__ __half g_x_h [(size_t)BATCH * CMID * HWP];  // pad cols stay 0
__device__ __half g_x_l [(size_t)BATCH * CMID * HWP];
__device__ __half g_xT_h[(size_t)BATCH * HW * CMID];
__device__ float  g_att [(size_t)BATCH * CMID * CMID];
__device__ __half g_att_h[(size_t)BATCH * CMID * CMID];
__device__ __half g_yT_h[(size_t)BATCH * HW * CMID];
__device__ __half g_w1_h[(size_t)CMID * CIN];
__device__ __half g_w1_l[(size_t)CMID * CIN];
__device__ __half g_w3_h[(size_t)CMID * K33];   // reordered k = rs*512 + c
__device__ float g_zsum[BATCH * CMID];
__device__ float g_h[BATCH * 200];
__device__ float g_scale1[CMID], g_shift1[CMID], g_scale3[CMID], g_shift3[CMID];

// ---------------- ptx helpers (all non-'a' gated: sm_80-level) --------------
__device__ __forceinline__ uint32_t smem_u32(const void* p) {
    uint32_t a;
    asm("{ .reg .u64 t; cvta.to.shared.u64 t, %1; cvt.u32.u64 %0, t; }"
        : "=r"(a) : "l"(p));
    return a;
}
__device__ __forceinline__ void cp16(uint32_t dst, const void* src) {
    asm volatile("cp.async.ca.shared.global [%0], [%1], 16;"
                 :: "r"(dst), "l"(src));
}
__device__ __forceinline__ void cp16z(uint32_t dst, const void* src, int ok) {
    int sz = ok ? 16 : 0;
    asm volatile("cp.async.ca.shared.global [%0], [%1], 16, %2;"
                 :: "r"(dst), "l"(src), "r"(sz));
}
__device__ __forceinline__ void cp_commit() {
    asm volatile("cp.async.commit_group;" ::: "memory");
}
template<int N> __device__ __forceinline__ void cp_wait() {
    asm volatile("cp.async.wait_group %0;" :: "n"(N) : "memory");
}
__device__ __forceinline__ void ldm4(uint32_t* r, uint32_t addr) {
    asm volatile("ldmatrix.sync.aligned.m8n8.x4.shared.b16 {%0,%1,%2,%3}, [%4];"
                 : "=r"(r[0]), "=r"(r[1]), "=r"(r[2]), "=r"(r[3]) : "r"(addr));
}
__device__ __forceinline__ void ldm2(uint32_t* r, uint32_t addr) {
    asm volatile("ldmatrix.sync.aligned.m8n8.x2.shared.b16 {%0,%1}, [%2];"
                 : "=r"(r[0]), "=r"(r[1]) : "r"(addr));
}
__device__ __forceinline__ void mma16816(float* c, const uint32_t* a,
                                         const uint32_t* b) {
    asm volatile(
        "mma.sync.aligned.m16n8k16.row.col.f32.f16.f16.f32 "
        "{%0,%1,%2,%3}, {%4,%5,%6,%7}, {%8,%9}, {%0,%1,%2,%3};"
        : "+f"(c[0]), "+f"(c[1]), "+f"(c[2]), "+f"(c[3])
        : "r"(a[0]), "r"(a[1]), "r"(a[2]), "r"(a[3]), "r"(b[0]), "r"(b[1]));
}
__device__ __forceinline__ void split_fp16(float v, __half& hi, __half& lo) {
    hi = __float2half_rn(v);
    lo = __float2half_rn(v - __half2float(hi));
}

// ---------------- SMEM geometry ---------------------------------------------
#define TROW 80
#define TILE_B (128 * TROW)          // 10240 B
#define STAGE_B (4 * TILE_B)         // Ah, Al, Bh, Bl (reduce/xxt)
#define STAGE2_B (2 * TILE_B)        // Ah, Bh         (ygemm/conv)
#define DYN_SMEM (2 * STAGE_B)       // 81920 B
#define DYN2_SMEM (2 * STAGE2_B)     // 40960 B (ygemm)
#define DYNC_SMEM (3 * STAGE2_B)     // 61440 B (conv, 3-stage)

// contiguous 128x32 tile load via cp.async: 512 16B chunks / 256 threads
__device__ __forceinline__ void cpa_tile(uint32_t sdst, const __half* g,
                                         size_t stride, int k0, int tid) {
    #pragma unroll
    for (int it = 0; it < 2; it++) {
        int ch = it * 256 + tid;
        int row = ch >> 2, seg = ch & 3;
        cp16(sdst + row * TROW + seg * 16,
             g + (size_t)row * stride + k0 + seg * 8);
    }
}
__device__ __forceinline__ void cpa_tile_clamp(uint32_t sdst, const __half* g,
                                               size_t stride, int row0,
                                               int maxrow, int k0, int tid) {
    #pragma unroll
    for (int it = 0; it < 2; it++) {
        int ch = it * 256 + tid;
        int row = ch >> 2, seg = ch & 3;
        int rg = row0 + row; if (rg > maxrow) rg = maxrow;
        cp16(sdst + row * TROW + seg * 16,
             g + (size_t)rg * stride + k0 + seg * 8);
    }
}

// one k16 slab: 4 m-atoms x 4 n-atoms of m16n8k16
__device__ __forceinline__ void mma_k16(uint32_t aBase, uint32_t bBase, int kk,
                                        int lane, float c[4][4][4]) {
    uint32_t a[4][4], b[4][2];
    int arow = lane & 15, asel = lane >> 4;
    #pragma unroll
    for (int am = 0; am < 4; am++)
        ldm4(a[am], aBase + (am * 16 + arow) * TROW + (kk + asel * 8) * 2);
    int brow = lane & 7, bsel = (lane >> 3) & 1;
    #pragma unroll
    for (int bn = 0; bn < 4; bn++)
        ldm2(b[bn], bBase + (bn * 8 + brow) * TROW + (kk + bsel * 8) * 2);
    #pragma unroll
    for (int am = 0; am < 4; am++)
        #pragma unroll
        for (int bn = 0; bn < 4; bn++)
            mma16816(c[am][bn], a[am], b[bn]);
}

// full 3-term stage (reduce/xxt): (Ah,Bh), (Ah,Bl), (Al,Bh)
__device__ __forceinline__ void stage_compute(uint32_t sb, int wm, int wn,
                                              int lane, float c[4][4][4]) {
    uint32_t Ah = sb + wm * TROW,              Al = Ah + TILE_B;
    uint32_t Bh = sb + 2 * TILE_B + wn * TROW, Bl = Bh + TILE_B;
    #pragma unroll
    for (int kk = 0; kk < 32; kk += 16) {
        mma_k16(Ah, Bh, kk, lane, c);
        mma_k16(Ah, Bl, kk, lane, c);
        mma_k16(Al, Bh, kk, lane, c);
    }
}
// 1-term stage (ygemm/conv): Ah x Bh
__device__ __forceinline__ void stage_compute_1(uint32_t sb, int wm, int wn,
                                                int lane, float c[4][4][4]) {
    uint32_t Ah = sb + wm * TROW;
    uint32_t Bh = sb + TILE_B + wn * TROW;
    #pragma unroll
    for (int kk = 0; kk < 32; kk += 16) mma_k16(Ah, Bh, kk, lane, c);
}

#define GEMM_VARS()                                                            \
    extern __shared__ __align__(16) char dsm[];                                \
    uint32_t sb0 = smem_u32(dsm);                                              \
    int tid = threadIdx.x, wid = tid >> 5, lane = tid & 31;                    \
    int wm = (wid >> 2) * 64, wn = (wid & 3) * 32;                             \
    float c[4][4][4] = {};

// ---------------- small prep kernels ----------------------------------------
__global__ void k_zero() {
    g_zsum[blockIdx.x * blockDim.x + threadIdx.x] = 0.f;
}
__global__ void prep_bn(const float* __restrict__ rb, const float* __restrict__ rg,
                        const float* __restrict__ rbe, const float* __restrict__ rm,
                        const float* __restrict__ rv,
                        const float* __restrict__ cb, const float* __restrict__ cg,
                        const float* __restrict__ cbe, const float* __restrict__ cm,
                        const float* __restrict__ cv) {
    int i = blockIdx.x * blockDim.x + threadIdx.x;
    if (i < CMID) {
        float inv = rg[i] * rsqrtf(rv[i] + EPS);
        g_scale1[i] = inv;
        g_shift1[i] = (rb[i] - rm[i]) * inv + rbe[i];
        float inv3 = cg[i] * rsqrtf(cv[i] + EPS);
        g_scale3[i] = inv3;
        g_shift3[i] = (cb[i] - cm[i]) * inv3 + cbe[i];
    }
}
__global__ void cvt_w1(const float* __restrict__ w) {
    int i = blockIdx.x * blockDim.x + threadIdx.x;
    __half hi, lo; split_fp16(w[i], hi, lo);
    g_w1_h[i] = hi; g_w1_l[i] = lo;
}
__global__ void cvt_w3(const float* __restrict__ w) {
    int i = blockIdx.x * blockDim.x + threadIdx.x;   // over 512*4608
    int o = i / K33, k = i - o * K33;
    int rs = k >> 9, cc = k & 511;
    int r = rs / 3, s = rs - r * 3;
    g_w3_h[i] = __float2half_rn(w[((o * CMID + cc) * 3 + r) * 3 + s]);
}
// transpose + split features: F[b][c][hw] -> g_fT[b*196+hw][c]
// vectorized: float4 reads (hw 4-aligned), int4 (8 x fp16) writes
__global__ __launch_bounds__(256) void cvt_f(const float* __restrict__ f2,
                                             const float* __restrict__ f3) {
    __shared__ float t[32][133];
    int hw0 = blockIdx.x * 128, c0 = blockIdx.y * 32, b = blockIdx.z;
    const float* F = (b < HB) ? f2 + (size_t)b * CIN * HW
                              : f3 + (size_t)(b - HB) * CIN * HW;
    int tid = threadIdx.x;
    int cc = tid >> 3, seg = tid & 7;
    const float* Frow = F + (size_t)(c0 + cc) * HW;
    #pragma unroll
    for (int q = 0; q < 4; q++) {
        int hwl = seg * 16 + q * 4;
        int hw = hw0 + hwl;
        float4 v = make_float4(0.f, 0.f, 0.f, 0.f);
        if (hw < HW) v = *reinterpret_cast<const float4*>(Frow + hw);  // 196%4==0
        t[cc][hwl + 0] = v.x; t[cc][hwl + 1] = v.y;
        t[cc][hwl + 2] = v.z; t[cc][hwl + 3] = v.w;
    }
    __syncthreads();
    int row = tid >> 1, cq = (tid & 1) * 16;
    int hw = hw0 + row;
    if (hw < HW) {
        __half hb[16], lb[16];
        #pragma unroll
        for (int e = 0; e < 16; e++) split_fp16(t[cq + e][row], hb[e], lb[e]);
        size_t idx = ((size_t)b * HW + hw) * CIN + c0 + cq;
        *reinterpret_cast<int4*>(g_fT_h + idx)     = *reinterpret_cast<int4*>(hb);
        *reinterpret_cast<int4*>(g_fT_h + idx + 8) = *reinterpret_cast<int4*>(hb + 8);
        *reinterpret_cast<int4*>(g_fT_l + idx)     = *reinterpret_cast<int4*>(lb);
        *reinterpret_cast<int4*>(g_fT_l + idx + 8) = *reinterpret_cast<int4*>(lb + 8);
    }
}

// ---------------- K1: reduce GEMM (M=512, N=25088, K=2048) + BN/ReLU --------
// grid (4 m, 196 n): m fastest -> 4 consecutive CTAs share each B tile in L2
__global__ __launch_bounds__(256, 2) void k_reduce_mma() {
    GEMM_VARS();
    int m0 = blockIdx.x * 128, n0 = blockIdx.y * 128;
    const int T = CIN / 32;    // 64 stages
    const __half* Awh = g_w1_h + (size_t)m0 * CIN;
    const __half* Awl = g_w1_l + (size_t)m0 * CIN;
    const __half* Bfh = g_fT_h + (size_t)n0 * CIN;
    const __half* Bfl = g_fT_l + (size_t)n0 * CIN;
    #define ISSUE(kt) {                                                        \
        uint32_t s = sb0 + ((kt) & 1) * STAGE_B; int k0 = (kt) * 32;           \
        cpa_tile(s,              Awh, CIN, k0, tid);                           \
        cpa_tile(s + TILE_B,     Awl, CIN, k0, tid);                           \
        cpa_tile(s + 2 * TILE_B, Bfh, CIN, k0, tid);                           \
        cpa_tile(s + 3 * TILE_B, Bfl, CIN, k0, tid); }
    ISSUE(0); cp_commit();
    for (int kt = 0; kt < T; kt++) {
        if (kt + 1 < T) { ISSUE(kt + 1); cp_commit(); cp_wait<1>(); }
        else cp_wait<0>();
        __syncthreads();
        stage_compute(sb0 + (kt & 1) * STAGE_B, wm, wn, lane, c);
        __syncthreads();
    }
    #undef ISSUE
    #pragma unroll
    for (int am = 0; am < 4; am++) {
        #pragma unroll
        for (int half = 0; half < 2; half++) {
            int o = m0 + wm + am * 16 + (lane >> 2) + half * 8;
            float sc = g_scale1[o], sh = g_shift1[o];
            #pragma unroll
            for (int bn = 0; bn < 4; bn++) {
                #pragma unroll
                for (int e = 0; e < 2; e++) {
                    float v = c[am][bn][half * 2 + e];
                    v = fmaxf(v * sc + sh, 0.f);
                    int col = n0 + wn + bn * 8 + 2 * (lane & 3) + e;
                    int b = col / HW, hw = col - b * HW;
                    __half hi, lo; split_fp16(v, hi, lo);
                    size_t i1 = ((size_t)b * CMID + o) * HWP + hw;
                    g_x_h[i1] = hi; g_x_l[i1] = lo;
                    g_xT_h[((size_t)b * HW + hw) * CMID + o] = hi;
                }
            }
        }
    }
}

// ---------------- K2: XXt per batch, SYMMETRIC: 10 upper-triangle tiles -----
__global__ __launch_bounds__(256, 2) void k_xxt_mma() {
    GEMM_VARS();
    const int TI[10] = {0, 0, 0, 0, 1, 1, 1, 2, 2, 3};
    const int TJ[10] = {0, 1, 2, 3, 1, 2, 3, 2, 3, 3};
    int m0 = TI[blockIdx.x] * 128, n0 = TJ[blockIdx.x] * 128;
    int b = blockIdx.z;
    const __half* Xh = g_x_h + (size_t)b * CMID * HWP;
    const __half* Xl = g_x_l + (size_t)b * CMID * HWP;
    const int T = KXT / 32;    // 7 stages
    #define ISSUE(kt) {                                                        \
        uint32_t s = sb0 + ((kt) & 1) * STAGE_B; int k0 = (kt) * 32;           \
        cpa_tile(s,              Xh + (size_t)m0 * HWP, HWP, k0, tid);         \
        cpa_tile(s + TILE_B,     Xl + (size_t)m0 * HWP, HWP, k0, tid);         \
        cpa_tile(s + 2 * TILE_B, Xh + (size_t)n0 * HWP, HWP, k0, tid);         \
        cpa_tile(s + 3 * TILE_B, Xl + (size_t)n0 * HWP, HWP, k0, tid); }
    ISSUE(0); cp_commit();
    for (int kt = 0; kt < T; kt++) {
        if (kt + 1 < T) { ISSUE(kt + 1); cp_commit(); cp_wait<1>(); }
        else cp_wait<0>();
        __syncthreads();
        stage_compute(sb0 + (kt & 1) * STAGE_B, wm, wn, lane, c);
        __syncthreads();
    }
    #undef ISSUE
    float* out = g_att + (size_t)b * CMID * CMID;
    if (m0 == n0) {
        #pragma unroll
        for (int am = 0; am < 4; am++)
            #pragma unroll
            for (int half = 0; half < 2; half++) {
                int r = m0 + wm + am * 16 + (lane >> 2) + half * 8;
                #pragma unroll
                for (int bn = 0; bn < 4; bn++) {
                    int col = n0 + wn + bn * 8 + 2 * (lane & 3);
                    out[(size_t)r * CMID + col]     = c[am][bn][half * 2 + 0];
                    out[(size_t)r * CMID + col + 1] = c[am][bn][half * 2 + 1];
                }
            }
    } else {
        // stage tile in smem, write (m0,n0) and transposed (n0,m0) coalesced
        float* st = reinterpret_cast<float*>(dsm);   // [128][129]
        #pragma unroll
        for (int am = 0; am < 4; am++)
            #pragma unroll
            for (int half = 0; half < 2; half++) {
                int r = wm + am * 16 + (lane >> 2) + half * 8;
                #pragma unroll
                for (int bn = 0; bn < 4; bn++) {
                    int col = wn + bn * 8 + 2 * (lane & 3);
                    st[r * 129 + col]     = c[am][bn][half * 2 + 0];
                    st[r * 129 + col + 1] = c[am][bn][half * 2 + 1];
                }
            }
        __syncthreads();
        for (int idx = tid; idx < 128 * 128; idx += 256) {
            int r = idx >> 7, cl = idx & 127;
            out[(size_t)(m0 + r) * CMID + n0 + cl] = st[r * 129 + cl];
        }
        for (int idx = tid; idx < 128 * 128; idx += 256) {
            int r = idx >> 7, cl = idx & 127;
            out[(size_t)(n0 + r) * CMID + m0 + cl] = st[cl * 129 + r];
        }
    }
}

// ---------------- K3: softmax(-S) rowwise -> fp16 (single) ------------------
__global__ __launch_bounds__(256) void k_softmax() {
    int gw = (blockIdx.x * blockDim.x + threadIdx.x) >> 5;
    int lane = threadIdx.x & 31;
    if (gw >= BATCH * CMID) return;
    const float* row = g_att + (size_t)gw * CMID;
    float mn = CUDART_INF_F;
    #pragma unroll
    for (int t = 0; t < 16; t++) mn = fminf(mn, row[lane + t * 32]);
    #pragma unroll
    for (int o = 16; o; o >>= 1) mn = fminf(mn, __shfl_xor_sync(~0u, mn, o));
    float e[16], sum = 0.f;
    #pragma unroll
    for (int t = 0; t < 16; t++) { e[t] = __expf(mn - row[lane + t * 32]); sum += e[t]; }
    #pragma unroll
    for (int o = 16; o; o >>= 1) sum += __shfl_xor_sync(~0u, sum, o);
    float inv = 1.f / sum;
    #pragma unroll
    for (int t = 0; t < 16; t++)
        g_att_h[(size_t)gw * CMID + lane + t * 32] = __float2half_rn(e[t] * inv);
}

// ---------------- K4: y = att @ X (M=512, N=196pad256, K=512), 1-term -------
__global__ __launch_bounds__(256, 2) void k_ygemm_mma() {
    GEMM_VARS();
    int n0 = blockIdx.x * 128, m0 = blockIdx.y * 128, b = blockIdx.z;
    const __half* Ah = g_att_h + ((size_t)b * CMID + m0) * CMID;
    const __half* Bh = g_xT_h + (size_t)b * HW * CMID;
    const int T = CMID / 32;   // 16 stages
    #define ISSUE(kt) {                                                        \
        uint32_t s = sb0 + ((kt) & 1) * STAGE2_B; int k0 = (kt) * 32;          \
        cpa_tile(s, Ah, CMID, k0, tid);                                        \
        cpa_tile_clamp(s + TILE_B, Bh, CMID, n0, HW - 1, k0, tid); }
    ISSUE(0); cp_commit();
    for (int kt = 0; kt < T; kt++) {
        if (kt + 1 < T) { ISSUE(kt + 1); cp_commit(); cp_wait<1>(); }
        else cp_wait<0>();
        __syncthreads();
        stage_compute_1(sb0 + (kt & 1) * STAGE2_B, wm, wn, lane, c);
        __syncthreads();
    }
    #undef ISSUE
    #pragma unroll
    for (int am = 0; am < 4; am++)
        #pragma unroll
        for (int half = 0; half < 2; half++) {
            int i = m0 + wm + am * 16 + (lane >> 2) + half * 8;
            #pragma unroll
            for (int bn = 0; bn < 4; bn++)
                #pragma unroll
                for (int e = 0; e < 2; e++) {
                    int col = n0 + wn + bn * 8 + 2 * (lane & 3) + e;
                    if (col < HW)
                        g_yT_h[((size_t)b * HW + col) * CMID + i] =
                            __float2half_rn(c[am][bn][half * 2 + e]);
                }
        }
}

// ---------------- K5: conv3 implicit GEMM (M=512, N=25088, K=4608), 1-term --
// grid (4 m, 196 n). 3-stage pipeline. K reordered (rs, c).
__global__ __launch_bounds__(256, 2) void k_conv_mma() {
    GEMM_VARS();
    int m0 = blockIdx.x * 128, n0 = blockIdx.y * 128;
    const int T = K33 / 32;    // 144 stages
    int gr[2], gb[2], gph[2], gpw[2];
    #pragma unroll
    for (int it = 0; it < 2; it++) {
        int row = it * 64 + (tid >> 2);
        gr[it] = row;
        int col = n0 + row;
        gb[it] = col / HW;
        int p = col - gb[it] * HW;
        gph[it] = p / 14; gpw[it] = p - gph[it] * 14;
    }
    int seg = tid & 3;
    #define ISSUE(kt) {                                                        \
        uint32_t s = sb0 + ((kt) % 3) * STAGE2_B; int k0 = (kt) * 32;          \
        cpa_tile(s, g_w3_h + (size_t)m0 * K33, K33, k0, tid);                  \
        int rs = (kt) >> 4, c0 = ((kt) & 15) * 32;                             \
        int dr = rs / 3 - 1, ds = rs - (rs / 3) * 3 - 1;                       \
        _Pragma("unroll")                                                      \
        for (int it = 0; it < 2; it++) {                                       \
            int ih = gph[it] + dr, iw = gpw[it] + ds;                          \
            int ok = ((unsigned)ih < 14u) && ((unsigned)iw < 14u);             \
            size_t pix = (size_t)gb[it] * HW + (ok ? ih * 14 + iw : 0);        \
            size_t gidx = pix * CMID + c0 + seg * 8;                           \
            cp16z(s + TILE_B + gr[it] * TROW + seg * 16, g_yT_h + gidx, ok);   \
        } }
    ISSUE(0); cp_commit();
    ISSUE(1); cp_commit();
    for (int kt = 0; kt < T; kt++) {
        if (kt + 2 < T) { ISSUE(kt + 2); cp_commit(); cp_wait<2>(); }
        else if (kt + 1 < T) cp_wait<1>();
        else cp_wait<0>();
        __syncthreads();
        stage_compute_1(sb0 + (kt % 3) * STAGE2_B, wm, wn, lane, c);
        __syncthreads();
    }
    #undef ISSUE
    // fused BN + ReLU + GAP
    int b0 = n0 / HW;
    int split = (b0 + 1) * HW - n0;   // local cols < split belong to b0
    #pragma unroll
    for (int am = 0; am < 4; am++)
        #pragma unroll
        for (int half = 0; half < 2; half++) {
            int o = m0 + wm + am * 16 + (lane >> 2) + half * 8;
            float sc = g_scale3[o], sh = g_shift3[o];
            float s0 = 0.f, s1 = 0.f;
            #pragma unroll
            for (int bn = 0; bn < 4; bn++)
                #pragma unroll
                for (int e = 0; e < 2; e++) {
                    float v = fmaxf(c[am][bn][half * 2 + e] * sc + sh, 0.f);
                    int lcol = wn + bn * 8 + 2 * (lane & 3) + e;
                    if (lcol < split) s0 += v; else s1 += v;
                }
            s0 += __shfl_xor_sync(~0u, s0, 1);
            s0 += __shfl_xor_sync(~0u, s0, 2);
            s1 += __shfl_xor_sync(~0u, s1, 1);
            s1 += __shfl_xor_sync(~0u, s1, 2);
            if ((lane & 3) == 0) {
                atomicAdd(&g_zsum[b0 * CMID + o], s0 * (1.f / HW));
                if (split < 128)
                    atomicAdd(&g_zsum[(b0 + 1) * CMID + o], s1 * (1.f / HW));
            }
        }
}

// ---------------- K7: fc1 + ReLU --------------------------------------------
__global__ __launch_bounds__(256) void k_fc1(const float* __restrict__ w,
                                             const float* __restrict__ bias) {
    int gw = (blockIdx.x * blockDim.x + threadIdx.x) >> 5;
    int lane = threadIdx.x & 31;
    if (gw >= BATCH * 200) return;
    int b = gw / 200, j = gw - b * 200;
    const float* zr = g_zsum + b * CMID;
    const float* wr = w + (size_t)j * CMID;
    float s = 0.f;
    for (int k = lane; k < CMID; k += 32) s += zr[k] * wr[k];
    #pragma unroll
    for (int o = 16; o; o >>= 1) s += __shfl_xor_sync(~0u, s, o);
    if (lane == 0) g_h[gw] = fmaxf(s + bias[j], 0.f);
}

// ---------------- K8: fc2 + branch-sum --------------------------------------
__global__ __launch_bounds__(256) void k_fc2(const float* __restrict__ w,
                                             const float* __restrict__ bias,
                                             float* __restrict__ out) {
    int gw = (blockIdx.x * blockDim.x + threadIdx.x) >> 5;
    int lane = threadIdx.x & 31;
    if (gw >= HB * 200) return;
    int b = gw / 200, j = gw - b * 200;
    const float* h1 = g_h + (size_t)b * 200;
    const float* h2 = g_h + (size_t)(b + HB) * 200;
    const float* wr = w + (size_t)j * 200;
    float s = 0.f;
    for (int k = lane; k < 200; k += 32) s += (h1[k] + h2[k]) * wr[k];
    #pragma unroll
    for (int o = 16; o; o >>= 1) s += __shfl_xor_sync(~0u, s, o);
    if (lane == 0) out[gw] = s + 2.f * bias[j];
}

// ---------------- launch ----------------------------------------------------
extern "C" void kernel_launch(void* const* d_in, const int* in_sizes, int n_in,
                              void* d_out, int out_size) {
    const float* f2  = (const float*)d_in[0];
    const float* f3  = (const float*)d_in[1];
    const float* rw  = (const float*)d_in[2];
    const float* rb  = (const float*)d_in[3];
    const float* rg  = (const float*)d_in[4];
    const float* rbe = (const float*)d_in[5];
    const float* rm  = (const float*)d_in[6];
    const float* rv  = (const float*)d_in[7];
    const float* c3w = (const float*)d_in[8];
    const float* c3b = (const float*)d_in[9];
    const float* c3g = (const float*)d_in[10];
    const float* c3be= (const float*)d_in[11];
    const float* c3m = (const float*)d_in[12];
    const float* c3v = (const float*)d_in[13];
    const float* f1w = (const float*)d_in[14];
    const float* f1b = (const float*)d_in[15];
    const float* f2w = (const float*)d_in[16];
    const float* f2b = (const float*)d_in[17];
    float* out = (float*)d_out;

    cudaFuncSetAttribute(k_reduce_mma, cudaFuncAttributeMaxDynamicSharedMemorySize, DYN_SMEM);
    cudaFuncSetAttribute(k_xxt_mma,    cudaFuncAttributeMaxDynamicSharedMemorySize, DYN_SMEM);
    cudaFuncSetAttribute(k_ygemm_mma,  cudaFuncAttributeMaxDynamicSharedMemorySize, DYN2_SMEM);
    cudaFuncSetAttribute(k_conv_mma,   cudaFuncAttributeMaxDynamicSharedMemorySize, DYNC_SMEM);

    k_zero<<<BATCH * CMID / 256, 256>>>();
    prep_bn<<<2, 256>>>(rb, rg, rbe, rm, rv, c3b, c3g, c3be, c3m, c3v);
    cvt_w1<<<(CMID * CIN) / 256, 256>>>(rw);
    cvt_w3<<<(CMID * K33) / 256, 256>>>(c3w);
    cvt_f<<<dim3(2, CIN / 32, BATCH), 256>>>(f2, f3);

    k_reduce_mma<<<dim3(4, NFLAT / 128), 256, DYN_SMEM>>>();
    k_xxt_mma<<<dim3(10, 1, BATCH), 256, DYN_SMEM>>>();
    k_softmax<<<(BATCH * CMID) / 8, 256>>>();
    k_ygemm_mma<<<dim3(2, 4, BATCH), 256, DYN2_SMEM>>>();
    k_conv_mma<<<dim3(4, NFLAT / 128), 256, DYNC_SMEM>>>();
    k_fc1<<<(BATCH * 200 + 7) / 8, 256>>>(f1w, f1b);
    k_fc2<<<(HB * 200 + 7) / 8, 256>>>(f2w, f2b, out);
}

// round 15
// speedup vs baseline: 1.1014x; 1.0156x over previous
#include <cuda_runtime.h>
#include <cuda_fp16.h>
#include <cstdint>
#include <math_constants.h>

#define EPS 1e-5f
#define HB 64
#define BATCH 128
#define CIN 2048
#define CMID 512
#define HW 196
#define HWP 256
#define KXT 224     // xxt effective K (>=196, /32)
#define K33 4608
#define NFLAT 25088   // 128*196 = 196 tiles of 128 exactly

// ---------------- scratch (static device globals; zero-init at load) --------
__device__ __half g_fT_h[(size_t)NFLAT * CIN];
__device__ __half g_fT_l[(size_t)NFLAT * CIN];
__device__ __half g_x_h [(size_t)BATCH * CMID * HWP];  // pad cols stay 0
__device__ __half g_x_l [(size_t)BATCH * CMID * HWP];
__device__ float  g_att [(size_t)BATCH * CMID * CMID];
__device__ __half g_att_h[(size_t)BATCH * CMID * CMID];
__device__ __half g_yT_h[(size_t)BATCH * HW * CMID];
__device__ __half g_w1_h[(size_t)CMID * CIN];
__device__ __half g_w1_l[(size_t)CMID * CIN];
__device__ __half g_w3_h[(size_t)CMID * K33];   // reordered k = rs*512 + c
__device__ float g_zsum[BATCH * CMID];
__device__ float g_h[BATCH * 200];
__device__ float g_scale1[CMID], g_shift1[CMID], g_scale3[CMID], g_shift3[CMID];

// ---------------- ptx helpers (all non-'a' gated: sm_80-level) --------------
__device__ __forceinline__ uint32_t smem_u32(const void* p) {
    uint32_t a;
    asm("{ .reg .u64 t; cvta.to.shared.u64 t, %1; cvt.u32.u64 %0, t; }"
        : "=r"(a) : "l"(p));
    return a;
}
__device__ __forceinline__ void cp16(uint32_t dst, const void* src) {
    asm volatile("cp.async.ca.shared.global [%0], [%1], 16;"
                 :: "r"(dst), "l"(src));
}
__device__ __forceinline__ void cp16z(uint32_t dst, const void* src, int ok) {
    int sz = ok ? 16 : 0;
    asm volatile("cp.async.ca.shared.global [%0], [%1], 16, %2;"
                 :: "r"(dst), "l"(src), "r"(sz));
}
__device__ __forceinline__ void cp_commit() {
    asm volatile("cp.async.commit_group;" ::: "memory");
}
template<int N> __device__ __forceinline__ void cp_wait() {
    asm volatile("cp.async.wait_group %0;" :: "n"(N) : "memory");
}
__device__ __forceinline__ void ldm4(uint32_t* r, uint32_t addr) {
    asm volatile("ldmatrix.sync.aligned.m8n8.x4.shared.b16 {%0,%1,%2,%3}, [%4];"
                 : "=r"(r[0]), "=r"(r[1]), "=r"(r[2]), "=r"(r[3]) : "r"(addr));
}
__device__ __forceinline__ void ldm4t(uint32_t* r, uint32_t addr) {
    asm volatile("ldmatrix.sync.aligned.m8n8.x4.trans.shared.b16 {%0,%1,%2,%3}, [%4];"
                 : "=r"(r[0]), "=r"(r[1]), "=r"(r[2]), "=r"(r[3]) : "r"(addr));
}
__device__ __forceinline__ void ldm2(uint32_t* r, uint32_t addr) {
    asm volatile("ldmatrix.sync.aligned.m8n8.x2.shared.b16 {%0,%1}, [%2];"
                 : "=r"(r[0]), "=r"(r[1]) : "r"(addr));
}
__device__ __forceinline__ void mma16816(float* c, const uint32_t* a,
                                         const uint32_t* b) {
    asm volatile(
        "mma.sync.aligned.m16n8k16.row.col.f32.f16.f16.f32 "
        "{%0,%1,%2,%3}, {%4,%5,%6,%7}, {%8,%9}, {%0,%1,%2,%3};"
        : "+f"(c[0]), "+f"(c[1]), "+f"(c[2]), "+f"(c[3])
        : "r"(a[0]), "r"(a[1]), "r"(a[2]), "r"(a[3]), "r"(b[0]), "r"(b[1]));
}
__device__ __forceinline__ void split_fp16(float v, __half& hi, __half& lo) {
    hi = __float2half_rn(v);
    lo = __float2half_rn(v - __half2float(hi));
}

// ---------------- SMEM geometry ---------------------------------------------
#define TROW 80
#define TILE_B (128 * TROW)          // 10240 B (K-major 128x32 tile)
#define STAGE_B (4 * TILE_B)         // reduce/xxt: Ah, Al, Bh, Bl
#define STAGE2_B (2 * TILE_B)        // conv: Ah, Bh
#define DYN_SMEM (2 * STAGE_B)       // 81920 B
#define DYNC_SMEM (3 * STAGE2_B)     // 61440 B (conv, 3-stage)
// ygemm: A = x tile [32 j][128 hw], pitch 272 B; B = att tile K-major (TROW)
#define XROW 272
#define XTILE_B (32 * XROW)          // 8704 B
#define STAGEY_B (XTILE_B + TILE_B)  // 18944 B
#define DYNY_SMEM (2 * STAGEY_B)     // 37888 B

// contiguous 128x32 K-major tile load via cp.async: 512 chunks / 256 threads
__device__ __forceinline__ void cpa_tile(uint32_t sdst, const __half* g,
                                         size_t stride, int k0, int tid) {
    #pragma unroll
    for (int it = 0; it < 2; it++) {
        int ch = it * 256 + tid;
        int row = ch >> 2, seg = ch & 3;
        cp16(sdst + row * TROW + seg * 16,
             g + (size_t)row * stride + k0 + seg * 8);
    }
}

// one k16 slab: 4 m-atoms x 4 n-atoms of m16n8k16 (A row-major, B K-major)
__device__ __forceinline__ void mma_k16(uint32_t aBase, uint32_t bBase, int kk,
                                        int lane, float c[4][4][4]) {
    uint32_t a[4][4], b[4][2];
    int arow = lane & 15, asel = lane >> 4;
    #pragma unroll
    for (int am = 0; am < 4; am++)
        ldm4(a[am], aBase + (am * 16 + arow) * TROW + (kk + asel * 8) * 2);
    int brow = lane & 7, bsel = (lane >> 3) & 1;
    #pragma unroll
    for (int bn = 0; bn < 4; bn++)
        ldm2(b[bn], bBase + (bn * 8 + brow) * TROW + (kk + bsel * 8) * 2);
    #pragma unroll
    for (int am = 0; am < 4; am++)
        #pragma unroll
        for (int bn = 0; bn < 4; bn++)
            mma16816(c[am][bn], a[am], b[bn]);
}
// one k16 slab with A loaded TRANSPOSED from S[k][m] (pitch XROW)
__device__ __forceinline__ void mma_k16_tA(uint32_t sA, uint32_t sB, int kk,
                                           int wm, int wn, int lane,
                                           float c[4][4][4]) {
    uint32_t a[4][4], b[4][2];
    int g = lane >> 3;
    int krow = kk + ((g >> 1) << 3) + (lane & 7);
    int mcol = ((g & 1) << 3);
    #pragma unroll
    for (int am = 0; am < 4; am++)
        ldm4t(a[am], sA + krow * XROW + (wm + am * 16 + mcol) * 2);
    int brow = lane & 7, bsel = (lane >> 3) & 1;
    #pragma unroll
    for (int bn = 0; bn < 4; bn++)
        ldm2(b[bn], sB + (wn + bn * 8 + brow) * TROW + (kk + bsel * 8) * 2);
    #pragma unroll
    for (int am = 0; am < 4; am++)
        #pragma unroll
        for (int bn = 0; bn < 4; bn++)
            mma16816(c[am][bn], a[am], b[bn]);
}

// full 3-term stage (reduce/xxt): (Ah,Bh), (Ah,Bl), (Al,Bh)
__device__ __forceinline__ void stage_compute(uint32_t sb, int wm, int wn,
                                              int lane, float c[4][4][4]) {
    uint32_t Ah = sb + wm * TROW,              Al = Ah + TILE_B;
    uint32_t Bh = sb + 2 * TILE_B + wn * TROW, Bl = Bh + TILE_B;
    #pragma unroll
    for (int kk = 0; kk < 32; kk += 16) {
        mma_k16(Ah, Bh, kk, lane, c);
        mma_k16(Ah, Bl, kk, lane, c);
        mma_k16(Al, Bh, kk, lane, c);
    }
}
// 1-term stage (conv): Ah x Bh
__device__ __forceinline__ void stage_compute_1(uint32_t sb, int wm, int wn,
                                                int lane, float c[4][4][4]) {
    uint32_t Ah = sb + wm * TROW;
    uint32_t Bh = sb + TILE_B + wn * TROW;
    #pragma unroll
    for (int kk = 0; kk < 32; kk += 16) mma_k16(Ah, Bh, kk, lane, c);
}

#define GEMM_VARS()                                                            \
    extern __shared__ __align__(16) char dsm[];                                \
    uint32_t sb0 = smem_u32(dsm);                                              \
    int tid = threadIdx.x, wid = tid >> 5, lane = tid & 31;                    \
    int wm = (wid >> 2) * 64, wn = (wid & 3) * 32;                             \
    float c[4][4][4] = {};

// ---------------- small prep kernels ----------------------------------------
__global__ void prep_bn(const float* __restrict__ rb, const float* __restrict__ rg,
                        const float* __restrict__ rbe, const float* __restrict__ rm,
                        const float* __restrict__ rv,
                        const float* __restrict__ cb, const float* __restrict__ cg,
                        const float* __restrict__ cbe, const float* __restrict__ cm,
                        const float* __restrict__ cv) {
    int i = blockIdx.x * blockDim.x + threadIdx.x;
    if (i < CMID) {
        float inv = rg[i] * rsqrtf(rv[i] + EPS);
        g_scale1[i] = inv;
        g_shift1[i] = (rb[i] - rm[i]) * inv + rbe[i];
        float inv3 = cg[i] * rsqrtf(cv[i] + EPS);
        g_scale3[i] = inv3;
        g_shift3[i] = (cb[i] - cm[i]) * inv3 + cbe[i];
    }
}
// w1 split + zsum zero folded in
__global__ void cvt_w1(const float* __restrict__ w) {
    int i = blockIdx.x * blockDim.x + threadIdx.x;
    __half hi, lo; split_fp16(w[i], hi, lo);
    g_w1_h[i] = hi; g_w1_l[i] = lo;
    if (i < BATCH * CMID) g_zsum[i] = 0.f;
}
__global__ void cvt_w3(const float* __restrict__ w) {
    int i = blockIdx.x * blockDim.x + threadIdx.x;   // over 512*4608
    int o = i / K33, k = i - o * K33;
    int rs = k >> 9, cc = k & 511;
    int r = rs / 3, s = rs - r * 3;
    g_w3_h[i] = __float2half_rn(w[((o * CMID + cc) * 3 + r) * 3 + s]);
}
// transpose + split features: F[b][c][hw] -> g_fT[b*196+hw][c]
__global__ __launch_bounds__(256) void cvt_f(const float* __restrict__ f2,
                                             const float* __restrict__ f3) {
    __shared__ float t[32][133];
    int hw0 = blockIdx.x * 128, c0 = blockIdx.y * 32, b = blockIdx.z;
    const float* F = (b < HB) ? f2 + (size_t)b * CIN * HW
                              : f3 + (size_t)(b - HB) * CIN * HW;
    int tid = threadIdx.x;
    int cc = tid >> 3, seg = tid & 7;
    const float* Frow = F + (size_t)(c0 + cc) * HW;
    #pragma unroll
    for (int q = 0; q < 4; q++) {
        int hwl = seg * 16 + q * 4;
        int hw = hw0 + hwl;
        float4 v = make_float4(0.f, 0.f, 0.f, 0.f);
        if (hw < HW) v = *reinterpret_cast<const float4*>(Frow + hw);  // 196%4==0
        t[cc][hwl + 0] = v.x; t[cc][hwl + 1] = v.y;
        t[cc][hwl + 2] = v.z; t[cc][hwl + 3] = v.w;
    }
    __syncthreads();
    int row = tid >> 1, cq = (tid & 1) * 16;
    int hw = hw0 + row;
    if (hw < HW) {
        __half hb[16], lb[16];
        #pragma unroll
        for (int e = 0; e < 16; e++) split_fp16(t[cq + e][row], hb[e], lb[e]);
        size_t idx = ((size_t)b * HW + hw) * CIN + c0 + cq;
        *reinterpret_cast<int4*>(g_fT_h + idx)     = *reinterpret_cast<int4*>(hb);
        *reinterpret_cast<int4*>(g_fT_h + idx + 8) = *reinterpret_cast<int4*>(hb + 8);
        *reinterpret_cast<int4*>(g_fT_l + idx)     = *reinterpret_cast<int4*>(lb);
        *reinterpret_cast<int4*>(g_fT_l + idx + 8) = *reinterpret_cast<int4*>(lb + 8);
    }
}

// ---------------- K1: reduce GEMM (M=512, N=25088, K=2048) + BN/ReLU --------
__global__ __launch_bounds__(256, 2) void k_reduce_mma() {
    GEMM_VARS();
    int m0 = blockIdx.x * 128, n0 = blockIdx.y * 128;
    const int T = CIN / 32;    // 64 stages
    const __half* Awh = g_w1_h + (size_t)m0 * CIN;
    const __half* Awl = g_w1_l + (size_t)m0 * CIN;
    const __half* Bfh = g_fT_h + (size_t)n0 * CIN;
    const __half* Bfl = g_fT_l + (size_t)n0 * CIN;
    #define ISSUE(kt) {                                                        \
        uint32_t s = sb0 + ((kt) & 1) * STAGE_B; int k0 = (kt) * 32;           \
        cpa_tile(s,              Awh, CIN, k0, tid);                           \
        cpa_tile(s + TILE_B,     Awl, CIN, k0, tid);                           \
        cpa_tile(s + 2 * TILE_B, Bfh, CIN, k0, tid);                           \
        cpa_tile(s + 3 * TILE_B, Bfl, CIN, k0, tid); }
    ISSUE(0); cp_commit();
    for (int kt = 0; kt < T; kt++) {
        if (kt + 1 < T) { ISSUE(kt + 1); cp_commit(); cp_wait<1>(); }
        else cp_wait<0>();
        __syncthreads();
        stage_compute(sb0 + (kt & 1) * STAGE_B, wm, wn, lane, c);
        __syncthreads();
    }
    #undef ISSUE
    #pragma unroll
    for (int am = 0; am < 4; am++) {
        #pragma unroll
        for (int half = 0; half < 2; half++) {
            int o = m0 + wm + am * 16 + (lane >> 2) + half * 8;
            float sc = g_scale1[o], sh = g_shift1[o];
            #pragma unroll
            for (int bn = 0; bn < 4; bn++) {
                #pragma unroll
                for (int e = 0; e < 2; e++) {
                    float v = c[am][bn][half * 2 + e];
                    v = fmaxf(v * sc + sh, 0.f);
                    int col = n0 + wn + bn * 8 + 2 * (lane & 3) + e;
                    int b = col / HW, hw = col - b * HW;
                    __half hi, lo; split_fp16(v, hi, lo);
                    size_t i1 = ((size_t)b * CMID + o) * HWP + hw;
                    g_x_h[i1] = hi; g_x_l[i1] = lo;
                }
            }
        }
    }
}

// ---------------- K2: XXt per batch, SYMMETRIC: 10 upper-triangle tiles -----
__global__ __launch_bounds__(256, 2) void k_xxt_mma() {
    GEMM_VARS();
    const int TI[10] = {0, 0, 0, 0, 1, 1, 1, 2, 2, 3};
    const int TJ[10] = {0, 1, 2, 3, 1, 2, 3, 2, 3, 3};
    int m0 = TI[blockIdx.x] * 128, n0 = TJ[blockIdx.x] * 128;
    int b = blockIdx.z;
    const __half* Xh = g_x_h + (size_t)b * CMID * HWP;
    const __half* Xl = g_x_l + (size_t)b * CMID * HWP;
    const int T = KXT / 32;    // 7 stages
    #define ISSUE(kt) {                                                        \
        uint32_t s = sb0 + ((kt) & 1) * STAGE_B; int k0 = (kt) * 32;           \
        cpa_tile(s,              Xh + (size_t)m0 * HWP, HWP, k0, tid);         \
        cpa_tile(s + TILE_B,     Xl + (size_t)m0 * HWP, HWP, k0, tid);         \
        cpa_tile(s + 2 * TILE_B, Xh + (size_t)n0 * HWP, HWP, k0, tid);         \
        cpa_tile(s + 3 * TILE_B, Xl + (size_t)n0 * HWP, HWP, k0, tid); }
    ISSUE(0); cp_commit();
    for (int kt = 0; kt < T; kt++) {
        if (kt + 1 < T) { ISSUE(kt + 1); cp_commit(); cp_wait<1>(); }
        else cp_wait<0>();
        __syncthreads();
        stage_compute(sb0 + (kt & 1) * STAGE_B, wm, wn, lane, c);
        __syncthreads();
    }
    #undef ISSUE
    float* out = g_att + (size_t)b * CMID * CMID;
    if (m0 == n0) {
        #pragma unroll
        for (int am = 0; am < 4; am++)
            #pragma unroll
            for (int half = 0; half < 2; half++) {
                int r = m0 + wm + am * 16 + (lane >> 2) + half * 8;
                #pragma unroll
                for (int bn = 0; bn < 4; bn++) {
                    int col = n0 + wn + bn * 8 + 2 * (lane & 3);
                    out[(size_t)r * CMID + col]     = c[am][bn][half * 2 + 0];
                    out[(size_t)r * CMID + col + 1] = c[am][bn][half * 2 + 1];
                }
            }
    } else {
        float* st = reinterpret_cast<float*>(dsm);   // [128][129]
        #pragma unroll
        for (int am = 0; am < 4; am++)
            #pragma unroll
            for (int half = 0; half < 2; half++) {
                int r = wm + am * 16 + (lane >> 2) + half * 8;
                #pragma unroll
                for (int bn = 0; bn < 4; bn++) {
                    int col = wn + bn * 8 + 2 * (lane & 3);
                    st[r * 129 + col]     = c[am][bn][half * 2 + 0];
                    st[r * 129 + col + 1] = c[am][bn][half * 2 + 1];
                }
            }
        __syncthreads();
        for (int idx = tid; idx < 128 * 128; idx += 256) {
            int r = idx >> 7, cl = idx & 127;
            out[(size_t)(m0 + r) * CMID + n0 + cl] = st[r * 129 + cl];
        }
        for (int idx = tid; idx < 128 * 128; idx += 256) {
            int r = idx >> 7, cl = idx & 127;
            out[(size_t)(n0 + r) * CMID + m0 + cl] = st[cl * 129 + r];
        }
    }
}

// ---------------- K3: softmax(-S) rowwise -> fp16, vectorized ----------------
__global__ __launch_bounds__(256) void k_softmax() {
    int gw = (blockIdx.x * blockDim.x + threadIdx.x) >> 5;
    int lane = threadIdx.x & 31;
    if (gw >= BATCH * CMID) return;
    const float* row = g_att + (size_t)gw * CMID + lane * 16;
    float v[16];
    #pragma unroll
    for (int q = 0; q < 4; q++)
        *reinterpret_cast<float4*>(v + q * 4) =
            *reinterpret_cast<const float4*>(row + q * 4);
    float mn = v[0];
    #pragma unroll
    for (int t = 1; t < 16; t++) mn = fminf(mn, v[t]);
    #pragma unroll
    for (int o = 16; o; o >>= 1) mn = fminf(mn, __shfl_xor_sync(~0u, mn, o));
    float e[16], sum = 0.f;
    #pragma unroll
    for (int t = 0; t < 16; t++) { e[t] = __expf(mn - v[t]); sum += e[t]; }
    #pragma unroll
    for (int o = 16; o; o >>= 1) sum += __shfl_xor_sync(~0u, sum, o);
    float inv = 1.f / sum;
    __half hb[16];
    #pragma unroll
    for (int t = 0; t < 16; t++) hb[t] = __float2half_rn(e[t] * inv);
    __half* dst = g_att_h + (size_t)gw * CMID + lane * 16;
    *reinterpret_cast<int4*>(dst)     = *reinterpret_cast<int4*>(hb);
    *reinterpret_cast<int4*>(dst + 8) = *reinterpret_cast<int4*>(hb + 8);
}

// ---------------- K4: yT = Xt @ attT (M=hw 196pad256, N=i 512, K=j 512) -----
// A = x channel-major tile, trans-ldmatrix; B = att row-major. Output coalesced.
__global__ __launch_bounds__(256, 2) void k_ygemm_mma() {
    GEMM_VARS();
    int hw0 = blockIdx.x * 128, n0 = blockIdx.y * 128, b = blockIdx.z;
    const __half* Xh = g_x_h + (size_t)b * CMID * HWP + hw0;
    const __half* At = g_att_h + ((size_t)b * CMID + n0) * CMID;
    const int T = CMID / 32;   // 16 stages over j
    #define ISSUE(kt) {                                                        \
        uint32_t s = sb0 + ((kt) & 1) * STAGEY_B; int k0 = (kt) * 32;          \
        _Pragma("unroll")                                                      \
        for (int it = 0; it < 2; it++) {                                       \
            int ch = it * 256 + tid;                                           \
            int row = ch >> 4, seg = ch & 15;                                  \
            cp16(s + row * XROW + seg * 16,                                    \
                 Xh + (size_t)(k0 + row) * HWP + seg * 8);                     \
        }                                                                      \
        cpa_tile(s + XTILE_B, At, CMID, k0, tid); }
    ISSUE(0); cp_commit();
    for (int kt = 0; kt < T; kt++) {
        if (kt + 1 < T) { ISSUE(kt + 1); cp_commit(); cp_wait<1>(); }
        else cp_wait<0>();
        __syncthreads();
        uint32_t s = sb0 + (kt & 1) * STAGEY_B;
        #pragma unroll
        for (int kk = 0; kk < 32; kk += 16)
            mma_k16_tA(s, s + XTILE_B, kk, wm, wn, lane, c);
        __syncthreads();
    }
    #undef ISSUE
    // coalesced yT write: rows = hw, cols = i (half2 pairs)
    #pragma unroll
    for (int am = 0; am < 4; am++)
        #pragma unroll
        for (int half = 0; half < 2; half++) {
            int hw = hw0 + wm + am * 16 + (lane >> 2) + half * 8;
            if (hw < HW) {
                __half* dst = g_yT_h + ((size_t)b * HW + hw) * CMID + n0;
                #pragma unroll
                for (int bn = 0; bn < 4; bn++) {
                    int i = wn + bn * 8 + 2 * (lane & 3);
                    __half2 p;
                    p.x = __float2half_rn(c[am][bn][half * 2 + 0]);
                    p.y = __float2half_rn(c[am][bn][half * 2 + 1]);
                    *reinterpret_cast<__half2*>(dst + i) = p;
                }
            }
        }
}

// ---------------- K5: conv3 implicit GEMM (M=512, N=25088, K=4608), 1-term --
// grid (4 m, 196 n). 3-stage pipeline. K reordered (rs, c).
__global__ __launch_bounds__(256, 2) void k_conv_mma() {
    GEMM_VARS();
    int m0 = blockIdx.x * 128, n0 = blockIdx.y * 128;
    const int T = K33 / 32;    // 144 stages
    int gr[2], gb[2], gph[2], gpw[2];
    #pragma unroll
    for (int it = 0; it < 2; it++) {
        int row = it * 64 + (tid >> 2);
        gr[it] = row;
        int col = n0 + row;
        gb[it] = col / HW;
        int p = col - gb[it] * HW;
        gph[it] = p / 14; gpw[it] = p - gph[it] * 14;
    }
    int seg = tid & 3;
    #define ISSUE(kt) {                                                        \
        uint32_t s = sb0 + ((kt) % 3) * STAGE2_B; int k0 = (kt) * 32;          \
        cpa_tile(s, g_w3_h + (size_t)m0 * K33, K33, k0, tid);                  \
        int rs = (kt) >> 4, c0 = ((kt) & 15) * 32;                             \
        int dr = rs / 3 - 1, ds = rs - (rs / 3) * 3 - 1;                       \
        _Pragma("unroll")                                                      \
        for (int it = 0; it < 2; it++) {                                       \
            int ih = gph[it] + dr, iw = gpw[it] + ds;                          \
            int ok = ((unsigned)ih < 14u) && ((unsigned)iw < 14u);             \
            size_t pix = (size_t)gb[it] * HW + (ok ? ih * 14 + iw : 0);        \
            size_t gidx = pix * CMID + c0 + seg * 8;                           \
            cp16z(s + TILE_B + gr[it] * TROW + seg * 16, g_yT_h + gidx, ok);   \
        } }
    ISSUE(0); cp_commit();
    ISSUE(1); cp_commit();
    for (int kt = 0; kt < T; kt++) {
        if (kt + 2 < T) { ISSUE(kt + 2); cp_commit(); cp_wait<2>(); }
        else if (kt + 1 < T) cp_wait<1>();
        else cp_wait<0>();
        __syncthreads();
        stage_compute_1(sb0 + (kt % 3) * STAGE2_B, wm, wn, lane, c);
        __syncthreads();
    }
    #undef ISSUE
    // fused BN + ReLU + GAP
    int b0 = n0 / HW;
    int split = (b0 + 1) * HW - n0;   // local cols < split belong to b0
    #pragma unroll
    for (int am = 0; am < 4; am++)
        #pragma unroll
        for (int half = 0; half < 2; half++) {
            int o = m0 + wm + am * 16 + (lane >> 2) + half * 8;
            float sc = g_scale3[o], sh = g_shift3[o];
            float s0 = 0.f, s1 = 0.f;
            #pragma unroll
            for (int bn = 0; bn < 4; bn++)
                #pragma unroll
                for (int e = 0; e < 2; e++) {
                    float v = fmaxf(c[am][bn][half * 2 + e] * sc + sh, 0.f);
                    int lcol = wn + bn * 8 + 2 * (lane & 3) + e;
                    if (lcol < split) s0 += v; else s1 += v;
                }
            s0 += __shfl_xor_sync(~0u, s0, 1);
            s0 += __shfl_xor_sync(~0u, s0, 2);
            s1 += __shfl_xor_sync(~0u, s1, 1);
            s1 += __shfl_xor_sync(~0u, s1, 2);
            if ((lane & 3) == 0) {
                atomicAdd(&g_zsum[b0 * CMID + o], s0 * (1.f / HW));
                if (split < 128)
                    atomicAdd(&g_zsum[(b0 + 1) * CMID + o], s1 * (1.f / HW));
            }
        }
}

// ---------------- K7: fc1 + ReLU --------------------------------------------
__global__ __launch_bounds__(256) void k_fc1(const float* __restrict__ w,
                                             const float* __restrict__ bias) {
    int gw = (blockIdx.x * blockDim.x + threadIdx.x) >> 5;
    int lane = threadIdx.x & 31;
    if (gw >= BATCH * 200) return;
    int b = gw / 200, j = gw - b * 200;
    const float* zr = g_zsum + b * CMID;
    const float* wr = w + (size_t)j * CMID;
    float s = 0.f;
    for (int k = lane; k < CMID; k += 32) s += zr[k] * wr[k];
    #pragma unroll
    for (int o = 16; o; o >>= 1) s += __shfl_xor_sync(~0u, s, o);
    if (lane == 0) g_h[gw] = fmaxf(s + bias[j], 0.f);
}

// ---------------- K8: fc2 + branch-sum --------------------------------------
__global__ __launch_bounds__(256) void k_fc2(const float* __restrict__ w,
                                             const float* __restrict__ bias,
                                             float* __restrict__ out) {
    int gw = (blockIdx.x * blockDim.x + threadIdx.x) >> 5;
    int lane = threadIdx.x & 31;
    if (gw >= HB * 200) return;
    int b = gw / 200, j = gw - b * 200;
    const float* h1 = g_h + (size_t)b * 200;
    const float* h2 = g_h + (size_t)(b + HB) * 200;
    const float* wr = w + (size_t)j * 200;
    float s = 0.f;
    for (int k = lane; k < 200; k += 32) s += (h1[k] + h2[k]) * wr[k];
    #pragma unroll
    for (int o = 16; o; o >>= 1) s += __shfl_xor_sync(~0u, s, o);
    if (lane == 0) out[gw] = s + 2.f * bias[j];
}

// ---------------- launch ----------------------------------------------------
extern "C" void kernel_launch(void* const* d_in, const int* in_sizes, int n_in,
                              void* d_out, int out_size) {
    const float* f2  = (const float*)d_in[0];
    const float* f3  = (const float*)d_in[1];
    const float* rw  = (const float*)d_in[2];
    const float* rb  = (const float*)d_in[3];
    const float* rg  = (const float*)d_in[4];
    const float* rbe = (const float*)d_in[5];
    const float* rm  = (const float*)d_in[6];
    const float* rv  = (const float*)d_in[7];
    const float* c3w = (const float*)d_in[8];
    const float* c3b = (const float*)d_in[9];
    const float* c3g = (const float*)d_in[10];
    const float* c3be= (const float*)d_in[11];
    const float* c3m = (const float*)d_in[12];
    const float* c3v = (const float*)d_in[13];
    const float* f1w = (const float*)d_in[14];
    const float* f1b = (const float*)d_in[15];
    const float* f2w = (const float*)d_in[16];
    const float* f2b = (const float*)d_in[17];
    float* out = (float*)d_out;

    cudaFuncSetAttribute(k_reduce_mma, cudaFuncAttributeMaxDynamicSharedMemorySize, DYN_SMEM);
    cudaFuncSetAttribute(k_xxt_mma,    cudaFuncAttributeMaxDynamicSharedMemorySize, DYN_SMEM);
    cudaFuncSetAttribute(k_ygemm_mma,  cudaFuncAttributeMaxDynamicSharedMemorySize, DYNY_SMEM);
    cudaFuncSetAttribute(k_conv_mma,   cudaFuncAttributeMaxDynamicSharedMemorySize, DYNC_SMEM);

    prep_bn<<<2, 256>>>(rb, rg, rbe, rm, rv, c3b, c3g, c3be, c3m, c3v);
    cvt_w1<<<(CMID * CIN) / 256, 256>>>(rw);
    cvt_w3<<<(CMID * K33) / 256, 256>>>(c3w);
    cvt_f<<<dim3(2, CIN / 32, BATCH), 256>>>(f2, f3);

    k_reduce_mma<<<dim3(4, NFLAT / 128), 256, DYN_SMEM>>>();
    k_xxt_mma<<<dim3(10, 1, BATCH), 256, DYN_SMEM>>>();
    k_softmax<<<(BATCH * CMID) / 8, 256>>>();
    k_ygemm_mma<<<dim3(2, 4, BATCH), 256, DYNY_SMEM>>>();
    k_conv_mma<<<dim3(4, NFLAT / 128), 256, DYNC_SMEM>>>();
    k_fc1<<<(BATCH * 200 + 7) / 8, 256>>>(f1w, f1b);
    k_fc2<<<(HB * 200 + 7) / 8, 256>>>(f2w, f2b, out);
}

// round 16
// speedup vs baseline: 1.1654x; 1.0582x over previous
#include <cuda_runtime.h>
#include <cuda_fp16.h>
#include <cstdint>
#include <math_constants.h>

#define EPS 1e-5f
#define HB 64
#define BATCH 128
#define CIN 2048
#define CMID 512
#define HW 196
#define HWP 256
#define KXT 224     // xxt effective K (>=196, /32)
#define K33 4608
#define NFLAT 25088   // 128*196 = 196 tiles of 128 exactly

// ---------------- scratch (static device globals; zero-init at load) --------
__device__ __half g_x_h [(size_t)BATCH * CMID * HWP];  // pad cols stay 0
__device__ __half g_x_l [(size_t)BATCH * CMID * HWP];
__device__ float  g_att [(size_t)BATCH * CMID * CMID];
__device__ __half g_att_h[(size_t)BATCH * CMID * CMID];
__device__ __half g_yT_h[(size_t)BATCH * HW * CMID];
__device__ __half g_w1_h[(size_t)CMID * CIN];
__device__ __half g_w1_l[(size_t)CMID * CIN];
__device__ __half g_w3_h[(size_t)CMID * K33];   // reordered k = rs*512 + c
__device__ float g_zsum[BATCH * CMID];
__device__ float g_h[BATCH * 200];
__device__ float g_scale1[CMID], g_shift1[CMID], g_scale3[CMID], g_shift3[CMID];

// ---------------- ptx helpers (all non-'a' gated: sm_80-level) --------------
__device__ __forceinline__ uint32_t smem_u32(const void* p) {
    uint32_t a;
    asm("{ .reg .u64 t; cvta.to.shared.u64 t, %1; cvt.u32.u64 %0, t; }"
        : "=r"(a) : "l"(p));
    return a;
}
__device__ __forceinline__ void cp16(uint32_t dst, const void* src) {
    asm volatile("cp.async.ca.shared.global [%0], [%1], 16;"
                 :: "r"(dst), "l"(src));
}
__device__ __forceinline__ void cp16z(uint32_t dst, const void* src, int ok) {
    int sz = ok ? 16 : 0;
    asm volatile("cp.async.ca.shared.global [%0], [%1], 16, %2;"
                 :: "r"(dst), "l"(src), "r"(sz));
}
__device__ __forceinline__ void cp_commit() {
    asm volatile("cp.async.commit_group;" ::: "memory");
}
template<int N> __device__ __forceinline__ void cp_wait() {
    asm volatile("cp.async.wait_group %0;" :: "n"(N) : "memory");
}
__device__ __forceinline__ void ldm4(uint32_t* r, uint32_t addr) {
    asm volatile("ldmatrix.sync.aligned.m8n8.x4.shared.b16 {%0,%1,%2,%3}, [%4];"
                 : "=r"(r[0]), "=r"(r[1]), "=r"(r[2]), "=r"(r[3]) : "r"(addr));
}
__device__ __forceinline__ void ldm4t(uint32_t* r, uint32_t addr) {
    asm volatile("ldmatrix.sync.aligned.m8n8.x4.trans.shared.b16 {%0,%1,%2,%3}, [%4];"
                 : "=r"(r[0]), "=r"(r[1]), "=r"(r[2]), "=r"(r[3]) : "r"(addr));
}
__device__ __forceinline__ void ldm2(uint32_t* r, uint32_t addr) {
    asm volatile("ldmatrix.sync.aligned.m8n8.x2.shared.b16 {%0,%1}, [%2];"
                 : "=r"(r[0]), "=r"(r[1]) : "r"(addr));
}
__device__ __forceinline__ void ldm2t(uint32_t* r, uint32_t addr) {
    asm volatile("ldmatrix.sync.aligned.m8n8.x2.trans.shared.b16 {%0,%1}, [%2];"
                 : "=r"(r[0]), "=r"(r[1]) : "r"(addr));
}
__device__ __forceinline__ void sts128(uint32_t a, int4 v) {
    asm volatile("st.shared.v4.b32 [%0], {%1,%2,%3,%4};"
                 :: "r"(a), "r"(v.x), "r"(v.y), "r"(v.z), "r"(v.w));
}
__device__ __forceinline__ void mma16816(float* c, const uint32_t* a,
                                         const uint32_t* b) {
    asm volatile(
        "mma.sync.aligned.m16n8k16.row.col.f32.f16.f16.f32 "
        "{%0,%1,%2,%3}, {%4,%5,%6,%7}, {%8,%9}, {%0,%1,%2,%3};"
        : "+f"(c[0]), "+f"(c[1]), "+f"(c[2]), "+f"(c[3])
        : "r"(a[0]), "r"(a[1]), "r"(a[2]), "r"(a[3]), "r"(b[0]), "r"(b[1]));
}
__device__ __forceinline__ void split_fp16(float v, __half& hi, __half& lo) {
    hi = __float2half_rn(v);
    lo = __float2half_rn(v - __half2float(hi));
}

// ---------------- SMEM geometry ---------------------------------------------
#define TROW 80
#define TILE_B (128 * TROW)          // 10240 B (K-major 128x32 tile)
#define STAGE_B (4 * TILE_B)         // xxt: Ah, Al, Bh, Bl
#define STAGE2_B (2 * TILE_B)        // conv: Ah, Bh
#define DYN_SMEM (2 * STAGE_B)       // 81920 B
#define DYNC_SMEM (3 * STAGE2_B)     // 61440 B (conv, 3-stage)
// ygemm: A = x tile [32 j][128 hw], pitch 272 B; B = att tile K-major (TROW)
#define XROW 272
#define XTILE_B (32 * XROW)          // 8704 B
#define STAGEY_B (XTILE_B + TILE_B)  // 18944 B
#define DYNY_SMEM (2 * STAGEY_B)     // 37888 B
// reduce: W tiles K-major (TROW), F tiles N-major 32k x 128n, 272 B rows
#define FROWB 272
#define FTILE_B (32 * FROWB)         // 8704 B
#define RFOFF_H (2 * TILE_B)         // 20480
#define RFOFF_L (RFOFF_H + FTILE_B)  // 29184
#define RSTAGE_B (2 * TILE_B + 2 * FTILE_B)  // 37888
#define RDYN_SMEM (2 * RSTAGE_B)     // 75776

// contiguous 128x32 K-major tile load via cp.async: 512 chunks / 256 threads
__device__ __forceinline__ void cpa_tile(uint32_t sdst, const __half* g,
                                         size_t stride, int k0, int tid) {
    #pragma unroll
    for (int it = 0; it < 2; it++) {
        int ch = it * 256 + tid;
        int row = ch >> 2, seg = ch & 3;
        cp16(sdst + row * TROW + seg * 16,
             g + (size_t)row * stride + k0 + seg * 8);
    }
}

// one k16 slab: 4 m-atoms x 4 n-atoms of m16n8k16 (A row-major, B K-major)
__device__ __forceinline__ void mma_k16(uint32_t aBase, uint32_t bBase, int kk,
                                        int lane, float c[4][4][4]) {
    uint32_t a[4][4], b[4][2];
    int arow = lane & 15, asel = lane >> 4;
    #pragma unroll
    for (int am = 0; am < 4; am++)
        ldm4(a[am], aBase + (am * 16 + arow) * TROW + (kk + asel * 8) * 2);
    int brow = lane & 7, bsel = (lane >> 3) & 1;
    #pragma unroll
    for (int bn = 0; bn < 4; bn++)
        ldm2(b[bn], bBase + (bn * 8 + brow) * TROW + (kk + bsel * 8) * 2);
    #pragma unroll
    for (int am = 0; am < 4; am++)
        #pragma unroll
        for (int bn = 0; bn < 4; bn++)
            mma16816(c[am][bn], a[am], b[bn]);
}
// one k16 slab, B fragments via ldm2t from N-major F tile (fBase includes wn*2)
__device__ __forceinline__ void mma_k16_t(uint32_t aBase, uint32_t fBase, int kk,
                                          int lane, float c[4][4][4]) {
    uint32_t a[4][4], b[4][2];
    int arow = lane & 15, asel = lane >> 4;
    #pragma unroll
    for (int am = 0; am < 4; am++)
        ldm4(a[am], aBase + (am * 16 + arow) * TROW + (kk + asel * 8) * 2);
    uint32_t frow = fBase + (kk + (lane & 15)) * FROWB;
    #pragma unroll
    for (int bn = 0; bn < 4; bn++)
        ldm2t(b[bn], frow + bn * 16);
    #pragma unroll
    for (int am = 0; am < 4; am++)
        #pragma unroll
        for (int bn = 0; bn < 4; bn++)
            mma16816(c[am][bn], a[am], b[bn]);
}
// one k16 slab with A loaded TRANSPOSED from S[k][m] (pitch XROW)
__device__ __forceinline__ void mma_k16_tA(uint32_t sA, uint32_t sB, int kk,
                                           int wm, int wn, int lane,
                                           float c[4][4][4]) {
    uint32_t a[4][4], b[4][2];
    int g = lane >> 3;
    int krow = kk + ((g >> 1) << 3) + (lane & 7);
    int mcol = ((g & 1) << 3);
    #pragma unroll
    for (int am = 0; am < 4; am++)
        ldm4t(a[am], sA + krow * XROW + (wm + am * 16 + mcol) * 2);
    int brow = lane & 7, bsel = (lane >> 3) & 1;
    #pragma unroll
    for (int bn = 0; bn < 4; bn++)
        ldm2(b[bn], sB + (wn + bn * 8 + brow) * TROW + (kk + bsel * 8) * 2);
    #pragma unroll
    for (int am = 0; am < 4; am++)
        #pragma unroll
        for (int bn = 0; bn < 4; bn++)
            mma16816(c[am][bn], a[am], b[bn]);
}

// 3-term stage (xxt): (Ah,Bh), (Ah,Bl), (Al,Bh)
__device__ __forceinline__ void stage_compute(uint32_t sb, int wm, int wn,
                                              int lane, float c[4][4][4]) {
    uint32_t Ah = sb + wm * TROW,              Al = Ah + TILE_B;
    uint32_t Bh = sb + 2 * TILE_B + wn * TROW, Bl = Bh + TILE_B;
    #pragma unroll
    for (int kk = 0; kk < 32; kk += 16) {
        mma_k16(Ah, Bh, kk, lane, c);
        mma_k16(Ah, Bl, kk, lane, c);
        mma_k16(Al, Bh, kk, lane, c);
    }
}
// 3-term stage (reduce): W K-major x F N-major
__device__ __forceinline__ void stage_reduce(uint32_t sb, int wm, int wn,
                                             int lane, float c[4][4][4]) {
    uint32_t Ah = sb + wm * TROW, Al = Ah + TILE_B;
    uint32_t Fh = sb + RFOFF_H + wn * 2, Fl = sb + RFOFF_L + wn * 2;
    #pragma unroll
    for (int kk = 0; kk < 32; kk += 16) {
        mma_k16_t(Ah, Fh, kk, lane, c);
        mma_k16_t(Ah, Fl, kk, lane, c);
        mma_k16_t(Al, Fh, kk, lane, c);
    }
}
// 1-term stage (conv): Ah x Bh
__device__ __forceinline__ void stage_compute_1(uint32_t sb, int wm, int wn,
                                                int lane, float c[4][4][4]) {
    uint32_t Ah = sb + wm * TROW;
    uint32_t Bh = sb + TILE_B + wn * TROW;
    #pragma unroll
    for (int kk = 0; kk < 32; kk += 16) mma_k16(Ah, Bh, kk, lane, c);
}

#define GEMM_VARS()                                                            \
    extern __shared__ __align__(16) char dsm[];                                \
    uint32_t sb0 = smem_u32(dsm);                                              \
    int tid = threadIdx.x, wid = tid >> 5, lane = tid & 31;                    \
    int wm = (wid >> 2) * 64, wn = (wid & 3) * 32;                             \
    float c[4][4][4] = {};

// ---------------- small prep kernels ----------------------------------------
__global__ void prep_bn(const float* __restrict__ rb, const float* __restrict__ rg,
                        const float* __restrict__ rbe, const float* __restrict__ rm,
                        const float* __restrict__ rv,
                        const float* __restrict__ cb, const float* __restrict__ cg,
                        const float* __restrict__ cbe, const float* __restrict__ cm,
                        const float* __restrict__ cv) {
    int i = blockIdx.x * blockDim.x + threadIdx.x;
    if (i < CMID) {
        float inv = rg[i] * rsqrtf(rv[i] + EPS);
        g_scale1[i] = inv;
        g_shift1[i] = (rb[i] - rm[i]) * inv + rbe[i];
        float inv3 = cg[i] * rsqrtf(cv[i] + EPS);
        g_scale3[i] = inv3;
        g_shift3[i] = (cb[i] - cm[i]) * inv3 + cbe[i];
    }
}
// w1 split + zsum zero folded in
__global__ void cvt_w1(const float* __restrict__ w) {
    int i = blockIdx.x * blockDim.x + threadIdx.x;
    __half hi, lo; split_fp16(w[i], hi, lo);
    g_w1_h[i] = hi; g_w1_l[i] = lo;
    if (i < BATCH * CMID) g_zsum[i] = 0.f;
}
__global__ void cvt_w3(const float* __restrict__ w) {
    int i = blockIdx.x * blockDim.x + threadIdx.x;   // over 512*4608
    int o = i / K33, k = i - o * K33;
    int rs = k >> 9, cc = k & 511;
    int r = rs / 3, s = rs - r * 3;
    g_w3_h[i] = __float2half_rn(w[((o * CMID + cc) * 3 + r) * 3 + s]);
}

// ---------------- K1: reduce GEMM (M=512, N=25088, K=2048) + BN/ReLU --------
// B read straight from fp32 features: HW%4==0 => every 4-aligned flattened
// chunk lies in ONE batch => 4 clean LDG.128 per thread, pointers hoisted.
__global__ __launch_bounds__(256, 2) void k_reduce_mma(const float* __restrict__ f2,
                                                       const float* __restrict__ f3) {
    GEMM_VARS();
    int m0 = blockIdx.x * 128, n0 = blockIdx.y * 128;
    const int T = CIN / 32;    // 64 stages
    const __half* Awh = g_w1_h + (size_t)m0 * CIN;
    const __half* Awl = g_w1_l + (size_t)m0 * CIN;

    int fk = tid >> 3;                      // k row 0..31
    uint32_t fcol = (uint32_t)(tid & 7) * 32u;  // byte col in F tile
    const float* pbase[4];
    #pragma unroll
    for (int q = 0; q < 4; q++) {
        int cg = n0 + (tid & 7) * 16 + q * 4;   // 4-aligned, single batch
        int b = cg / HW, hw = cg - b * HW;
        const float* F = (b < HB) ? f2 + (size_t)b * CIN * HW
                                  : f3 + (size_t)(b - HB) * CIN * HW;
        pbase[q] = F + hw;
    }

    float fr[16];
    #define LDF(kt) {                                                          \
        size_t ko = (size_t)((kt) * 32 + fk) * HW;                             \
        _Pragma("unroll")                                                      \
        for (int q = 0; q < 4; q++)                                            \
            *reinterpret_cast<float4*>(fr + q * 4) =                           \
                *reinterpret_cast<const float4*>(pbase[q] + ko);               \
    }
    #define STSF(s) {                                                          \
        uint32_t ph[8], pl[8];                                                 \
        _Pragma("unroll")                                                      \
        for (int e = 0; e < 8; e++) {                                          \
            __half h0_, l0_, h1_, l1_;                                         \
            split_fp16(fr[2 * e], h0_, l0_);                                   \
            split_fp16(fr[2 * e + 1], h1_, l1_);                               \
            __half2 hh = __halves2half2(h0_, h1_);                             \
            __half2 ll = __halves2half2(l0_, l1_);                             \
            ph[e] = *reinterpret_cast<uint32_t*>(&hh);                         \
            pl[e] = *reinterpret_cast<uint32_t*>(&ll);                         \
        }                                                                      \
        uint32_t fa = (s) + RFOFF_H + (uint32_t)fk * FROWB + fcol;             \
        sts128(fa,      make_int4(ph[0], ph[1], ph[2], ph[3]));                \
        sts128(fa + 16, make_int4(ph[4], ph[5], ph[6], ph[7]));                \
        fa += (RFOFF_L - RFOFF_H);                                             \
        sts128(fa,      make_int4(pl[0], pl[1], pl[2], pl[3]));                \
        sts128(fa + 16, make_int4(pl[4], pl[5], pl[6], pl[7]));                \
    }
    #define ISSUEW(kt) {                                                       \
        uint32_t s = sb0 + ((kt) & 1) * RSTAGE_B; int k0 = (kt) * 32;          \
        cpa_tile(s,          Awh, CIN, k0, tid);                               \
        cpa_tile(s + TILE_B, Awl, CIN, k0, tid);                               \
        cp_commit(); }

    LDF(0);
    ISSUEW(0);
    for (int kt = 0; kt < T; kt++) {
        uint32_t s = sb0 + (kt & 1) * RSTAGE_B;
        STSF(s);
        if (kt + 1 < T) LDF(kt + 1);
        cp_wait<0>();
        __syncthreads();
        if (kt + 1 < T) ISSUEW(kt + 1);
        stage_reduce(s, wm, wn, lane, c);
        __syncthreads();
    }
    #undef LDF
    #undef STSF
    #undef ISSUEW
    #pragma unroll
    for (int am = 0; am < 4; am++) {
        #pragma unroll
        for (int half = 0; half < 2; half++) {
            int o = m0 + wm + am * 16 + (lane >> 2) + half * 8;
            float sc = g_scale1[o], sh = g_shift1[o];
            #pragma unroll
            for (int bn = 0; bn < 4; bn++) {
                #pragma unroll
                for (int e = 0; e < 2; e++) {
                    float v = c[am][bn][half * 2 + e];
                    v = fmaxf(v * sc + sh, 0.f);
                    int col = n0 + wn + bn * 8 + 2 * (lane & 3) + e;
                    int b = col / HW, hw = col - b * HW;
                    __half hi, lo; split_fp16(v, hi, lo);
                    size_t i1 = ((size_t)b * CMID + o) * HWP + hw;
                    g_x_h[i1] = hi; g_x_l[i1] = lo;
                }
            }
        }
    }
}

// ---------------- K2: XXt per batch, SYMMETRIC: 10 upper-triangle tiles -----
__global__ __launch_bounds__(256, 2) void k_xxt_mma() {
    GEMM_VARS();
    const int TI[10] = {0, 0, 0, 0, 1, 1, 1, 2, 2, 3};
    const int TJ[10] = {0, 1, 2, 3, 1, 2, 3, 2, 3, 3};
    int m0 = TI[blockIdx.x] * 128, n0 = TJ[blockIdx.x] * 128;
    int b = blockIdx.z;
    const __half* Xh = g_x_h + (size_t)b * CMID * HWP;
    const __half* Xl = g_x_l + (size_t)b * CMID * HWP;
    const int T = KXT / 32;    // 7 stages
    #define ISSUE(kt) {                                                        \
        uint32_t s = sb0 + ((kt) & 1) * STAGE_B; int k0 = (kt) * 32;           \
        cpa_tile(s,              Xh + (size_t)m0 * HWP, HWP, k0, tid);         \
        cpa_tile(s + TILE_B,     Xl + (size_t)m0 * HWP, HWP, k0, tid);         \
        cpa_tile(s + 2 * TILE_B, Xh + (size_t)n0 * HWP, HWP, k0, tid);         \
        cpa_tile(s + 3 * TILE_B, Xl + (size_t)n0 * HWP, HWP, k0, tid); }
    ISSUE(0); cp_commit();
    for (int kt = 0; kt < T; kt++) {
        if (kt + 1 < T) { ISSUE(kt + 1); cp_commit(); cp_wait<1>(); }
        else cp_wait<0>();
        __syncthreads();
        stage_compute(sb0 + (kt & 1) * STAGE_B, wm, wn, lane, c);
        __syncthreads();
    }
    #undef ISSUE
    float* out = g_att + (size_t)b * CMID * CMID;
    if (m0 == n0) {
        #pragma unroll
        for (int am = 0; am < 4; am++)
            #pragma unroll
            for (int half = 0; half < 2; half++) {
                int r = m0 + wm + am * 16 + (lane >> 2) + half * 8;
                #pragma unroll
                for (int bn = 0; bn < 4; bn++) {
                    int col = n0 + wn + bn * 8 + 2 * (lane & 3);
                    out[(size_t)r * CMID + col]     = c[am][bn][half * 2 + 0];
                    out[(size_t)r * CMID + col + 1] = c[am][bn][half * 2 + 1];
                }
            }
    } else {
        float* st = reinterpret_cast<float*>(dsm);   // [128][129]
        #pragma unroll
        for (int am = 0; am < 4; am++)
            #pragma unroll
            for (int half = 0; half < 2; half++) {
                int r = wm + am * 16 + (lane >> 2) + half * 8;
                #pragma unroll
                for (int bn = 0; bn < 4; bn++) {
                    int col = wn + bn * 8 + 2 * (lane & 3);
                    st[r * 129 + col]     = c[am][bn][half * 2 + 0];
                    st[r * 129 + col + 1] = c[am][bn][half * 2 + 1];
                }
            }
        __syncthreads();
        for (int idx = tid; idx < 128 * 128; idx += 256) {
            int r = idx >> 7, cl = idx & 127;
            out[(size_t)(m0 + r) * CMID + n0 + cl] = st[r * 129 + cl];
        }
        for (int idx = tid; idx < 128 * 128; idx += 256) {
            int r = idx >> 7, cl = idx & 127;
            out[(size_t)(n0 + r) * CMID + m0 + cl] = st[cl * 129 + r];
        }
    }
}

// ---------------- K3: softmax(-S) rowwise -> fp16, vectorized ----------------
__global__ __launch_bounds__(256) void k_softmax() {
    int gw = (blockIdx.x * blockDim.x + threadIdx.x) >> 5;
    int lane = threadIdx.x & 31;
    if (gw >= BATCH * CMID) return;
    const float* row = g_att + (size_t)gw * CMID + lane * 16;
    float v[16];
    #pragma unroll
    for (int q = 0; q < 4; q++)
        *reinterpret_cast<float4*>(v + q * 4) =
            *reinterpret_cast<const float4*>(row + q * 4);
    float mn = v[0];
    #pragma unroll
    for (int t = 1; t < 16; t++) mn = fminf(mn, v[t]);
    #pragma unroll
    for (int o = 16; o; o >>= 1) mn = fminf(mn, __shfl_xor_sync(~0u, mn, o));
    float e[16], sum = 0.f;
    #pragma unroll
    for (int t = 0; t < 16; t++) { e[t] = __expf(mn - v[t]); sum += e[t]; }
    #pragma unroll
    for (int o = 16; o; o >>= 1) sum += __shfl_xor_sync(~0u, sum, o);
    float inv = 1.f / sum;
    __half hb[16];
    #pragma unroll
    for (int t = 0; t < 16; t++) hb[t] = __float2half_rn(e[t] * inv);
    __half* dst = g_att_h + (size_t)gw * CMID + lane * 16;
    *reinterpret_cast<int4*>(dst)     = *reinterpret_cast<int4*>(hb);
    *reinterpret_cast<int4*>(dst + 8) = *reinterpret_cast<int4*>(hb + 8);
}

// ---------------- K4: yT = Xt @ attT (M=hw 196pad256, N=i 512, K=j 512) -----
__global__ __launch_bounds__(256, 2) void k_ygemm_mma() {
    GEMM_VARS();
    int hw0 = blockIdx.x * 128, n0 = blockIdx.y * 128, b = blockIdx.z;
    const __half* Xh = g_x_h + (size_t)b * CMID * HWP + hw0;
    const __half* At = g_att_h + ((size_t)b * CMID + n0) * CMID;
    const int T = CMID / 32;   // 16 stages over j
    #define ISSUE(kt) {                                                        \
        uint32_t s = sb0 + ((kt) & 1) * STAGEY_B; int k0 = (kt) * 32;          \
        _Pragma("unroll")                                                      \
        for (int it = 0; it < 2; it++) {                                       \
            int ch = it * 256 + tid;                                           \
            int row = ch >> 4, seg = ch & 15;                                  \
            cp16(s + row * XROW + seg * 16,                                    \
                 Xh + (size_t)(k0 + row) * HWP + seg * 8);                     \
        }                                                                      \
        cpa_tile(s + XTILE_B, At, CMID, k0, tid); }
    ISSUE(0); cp_commit();
    for (int kt = 0; kt < T; kt++) {
        if (kt + 1 < T) { ISSUE(kt + 1); cp_commit(); cp_wait<1>(); }
        else cp_wait<0>();
        __syncthreads();
        uint32_t s = sb0 + (kt & 1) * STAGEY_B;
        #pragma unroll
        for (int kk = 0; kk < 32; kk += 16)
            mma_k16_tA(s, s + XTILE_B, kk, wm, wn, lane, c);
        __syncthreads();
    }
    #undef ISSUE
    #pragma unroll
    for (int am = 0; am < 4; am++)
        #pragma unroll
        for (int half = 0; half < 2; half++) {
            int hw = hw0 + wm + am * 16 + (lane >> 2) + half * 8;
            if (hw < HW) {
                __half* dst = g_yT_h + ((size_t)b * HW + hw) * CMID + n0;
                #pragma unroll
                for (int bn = 0; bn < 4; bn++) {
                    int i = wn + bn * 8 + 2 * (lane & 3);
                    __half2 p;
                    p.x = __float2half_rn(c[am][bn][half * 2 + 0]);
                    p.y = __float2half_rn(c[am][bn][half * 2 + 1]);
                    *reinterpret_cast<__half2*>(dst + i) = p;
                }
            }
        }
}

// ---------------- K5: conv3 implicit GEMM (M=512, N=25088, K=4608), 1-term --
__global__ __launch_bounds__(256, 2) void k_conv_mma() {
    GEMM_VARS();
    int m0 = blockIdx.x * 128, n0 = blockIdx.y * 128;
    const int T = K33 / 32;    // 144 stages
    int gr[2], gb[2], gph[2], gpw[2];
    #pragma unroll
    for (int it = 0; it < 2; it++) {
        int row = it * 64 + (tid >> 2);
        gr[it] = row;
        int col = n0 + row;
        gb[it] = col / HW;
        int p = col - gb[it] * HW;
        gph[it] = p / 14; gpw[it] = p - gph[it] * 14;
    }
    int seg = tid & 3;
    #define ISSUE(kt) {                                                        \
        uint32_t s = sb0 + ((kt) % 3) * STAGE2_B; int k0 = (kt) * 32;          \
        cpa_tile(s, g_w3_h + (size_t)m0 * K33, K33, k0, tid);                  \
        int rs = (kt) >> 4, c0 = ((kt) & 15) * 32;                             \
        int dr = rs / 3 - 1, ds = rs - (rs / 3) * 3 - 1;                       \
        _Pragma("unroll")                                                      \
        for (int it = 0; it < 2; it++) {                                       \
            int ih = gph[it] + dr, iw = gpw[it] + ds;                          \
            int ok = ((unsigned)ih < 14u) && ((unsigned)iw < 14u);             \
            size_t pix = (size_t)gb[it] * HW + (ok ? ih * 14 + iw : 0);        \
            size_t gidx = pix * CMID + c0 + seg * 8;                           \
            cp16z(s + TILE_B + gr[it] * TROW + seg * 16, g_yT_h + gidx, ok);   \
        } }
    ISSUE(0); cp_commit();
    ISSUE(1); cp_commit();
    for (int kt = 0; kt < T; kt++) {
        if (kt + 2 < T) { ISSUE(kt + 2); cp_commit(); cp_wait<2>(); }
        else if (kt + 1 < T) cp_wait<1>();
        else cp_wait<0>();
        __syncthreads();
        stage_compute_1(sb0 + (kt % 3) * STAGE2_B, wm, wn, lane, c);
        __syncthreads();
    }
    #undef ISSUE
    int b0 = n0 / HW;
    int split = (b0 + 1) * HW - n0;   // local cols < split belong to b0
    #pragma unroll
    for (int am = 0; am < 4; am++)
        #pragma unroll
        for (int half = 0; half < 2; half++) {
            int o = m0 + wm + am * 16 + (lane >> 2) + half * 8;
            float sc = g_scale3[o], sh = g_shift3[o];
            float s0 = 0.f, s1 = 0.f;
            #pragma unroll
            for (int bn = 0; bn < 4; bn++)
                #pragma unroll
                for (int e = 0; e < 2; e++) {
                    float v = fmaxf(c[am][bn][half * 2 + e] * sc + sh, 0.f);
                    int lcol = wn + bn * 8 + 2 * (lane & 3) + e;
                    if (lcol < split) s0 += v; else s1 += v;
                }
            s0 += __shfl_xor_sync(~0u, s0, 1);
            s0 += __shfl_xor_sync(~0u, s0, 2);
            s1 += __shfl_xor_sync(~0u, s1, 1);
            s1 += __shfl_xor_sync(~0u, s1, 2);
            if ((lane & 3) == 0) {
                atomicAdd(&g_zsum[b0 * CMID + o], s0 * (1.f / HW));
                if (split < 128)
                    atomicAdd(&g_zsum[(b0 + 1) * CMID + o], s1 * (1.f / HW));
            }
        }
}

// ---------------- K7: fc1 + ReLU --------------------------------------------
__global__ __launch_bounds__(256) void k_fc1(const float* __restrict__ w,
                                             const float* __restrict__ bias) {
    int gw = (blockIdx.x * blockDim.x + threadIdx.x) >> 5;
    int lane = threadIdx.x & 31;
    if (gw >= BATCH * 200) return;
    int b = gw / 200, j = gw - b * 200;
    const float* zr = g_zsum + b * CMID;
    const float* wr = w + (size_t)j * CMID;
    float s = 0.f;
    for (int k = lane; k < CMID; k += 32) s += zr[k] * wr[k];
    #pragma unroll
    for (int o = 16; o; o >>= 1) s += __shfl_xor_sync(~0u, s, o);
    if (lane == 0) g_h[gw] = fmaxf(s + bias[j], 0.f);
}

// ---------------- K8: fc2 + branch-sum --------------------------------------
__global__ __launch_bounds__(256) void k_fc2(const float* __restrict__ w,
                                             const float* __restrict__ bias,
                                             float* __restrict__ out) {
    int gw = (blockIdx.x * blockDim.x + threadIdx.x) >> 5;
    int lane = threadIdx.x & 31;
    if (gw >= HB * 200) return;
    int b = gw / 200, j = gw - b * 200;
    const float* h1 = g_h + (size_t)b * 200;
    const float* h2 = g_h + (size_t)(b + HB) * 200;
    const float* wr = w + (size_t)j * 200;
    float s = 0.f;
    for (int k = lane; k < 200; k += 32) s += (h1[k] + h2[k]) * wr[k];
    #pragma unroll
    for (int o = 16; o; o >>= 1) s += __shfl_xor_sync(~0u, s, o);
    if (lane == 0) out[gw] = s + 2.f * bias[j];
}

// ---------------- launch ----------------------------------------------------
extern "C" void kernel_launch(void* const* d_in, const int* in_sizes, int n_in,
                              void* d_out, int out_size) {
    const float* f2  = (const float*)d_in[0];
    const float* f3  = (const float*)d_in[1];
    const float* rw  = (const float*)d_in[2];
    const float* rb  = (const float*)d_in[3];
    const float* rg  = (const float*)d_in[4];
    const float* rbe = (const float*)d_in[5];
    const float* rm  = (const float*)d_in[6];
    const float* rv  = (const float*)d_in[7];
    const float* c3w = (const float*)d_in[8];
    const float* c3b = (const float*)d_in[9];
    const float* c3g = (const float*)d_in[10];
    const float* c3be= (const float*)d_in[11];
    const float* c3m = (const float*)d_in[12];
    const float* c3v = (const float*)d_in[13];
    const float* f1w = (const float*)d_in[14];
    const float* f1b = (const float*)d_in[15];
    const float* f2w = (const float*)d_in[16];
    const float* f2b = (const float*)d_in[17];
    float* out = (float*)d_out;

    cudaFuncSetAttribute(k_reduce_mma, cudaFuncAttributeMaxDynamicSharedMemorySize, RDYN_SMEM);
    cudaFuncSetAttribute(k_xxt_mma,    cudaFuncAttributeMaxDynamicSharedMemorySize, DYN_SMEM);
    cudaFuncSetAttribute(k_ygemm_mma,  cudaFuncAttributeMaxDynamicSharedMemorySize, DYNY_SMEM);
    cudaFuncSetAttribute(k_conv_mma,   cudaFuncAttributeMaxDynamicSharedMemorySize, DYNC_SMEM);

    prep_bn<<<2, 256>>>(rb, rg, rbe, rm, rv, c3b, c3g, c3be, c3m, c3v);
    cvt_w1<<<(CMID * CIN) / 256, 256>>>(rw);
    cvt_w3<<<(CMID * K33) / 256, 256>>>(c3w);

    k_reduce_mma<<<dim3(4, NFLAT / 128), 256, RDYN_SMEM>>>(f2, f3);
    k_xxt_mma<<<dim3(10, 1, BATCH), 256, DYN_SMEM>>>();
    k_softmax<<<(BATCH * CMID) / 8, 256>>>();
    k_ygemm_mma<<<dim3(2, 4, BATCH), 256, DYNY_SMEM>>>();
    k_conv_mma<<<dim3(4, NFLAT / 128), 256, DYNC_SMEM>>>();
    k_fc1<<<(BATCH * 200 + 7) / 8, 256>>>(f1w, f1b);
    k_fc2<<<(HB * 200 + 7) / 8, 256>>>(f2w, f2b, out);
}

// round 17
// speedup vs baseline: 1.2022x; 1.0315x over previous
#include <cuda_runtime.h>
#include <cuda_fp16.h>
#include <cstdint>
#include <math_constants.h>

#define EPS 1e-5f
#define HB 64
#define BATCH 128
#define CIN 2048
#define CMID 512
#define HW 196
#define HWP 256
#define KXT 224     // xxt effective K (>=196, /32)
#define K33 4608
#define NFLAT 25088   // 128*196 = 196 tiles of 128 exactly

// ---------------- scratch (static device globals; zero-init at load) --------
__device__ __half g_x_h [(size_t)BATCH * CMID * HWP];  // pad cols stay 0
__device__ __half g_x_l [(size_t)BATCH * CMID * HWP];
__device__ float  g_att [(size_t)BATCH * CMID * CMID];
__device__ __half g_att_h[(size_t)BATCH * CMID * CMID];
__device__ __half g_yT_h[(size_t)BATCH * HW * CMID];
__device__ __half g_w1_h[(size_t)CMID * CIN];
__device__ __half g_w1_l[(size_t)CMID * CIN];
__device__ __half g_w3_h[(size_t)CMID * K33];   // reordered k = rs*512 + c
__device__ float g_zsum[BATCH * CMID];
__device__ float g_h[BATCH * 200];
__device__ float g_scale1[CMID], g_shift1[CMID], g_scale3[CMID], g_shift3[CMID];

// ---------------- ptx helpers (all non-'a' gated: sm_80-level) --------------
__device__ __forceinline__ uint32_t smem_u32(const void* p) {
    uint32_t a;
    asm("{ .reg .u64 t; cvta.to.shared.u64 t, %1; cvt.u32.u64 %0, t; }"
        : "=r"(a) : "l"(p));
    return a;
}
__device__ __forceinline__ void cp16(uint32_t dst, const void* src) {
    asm volatile("cp.async.ca.shared.global [%0], [%1], 16;"
                 :: "r"(dst), "l"(src));
}
__device__ __forceinline__ void cp16z(uint32_t dst, const void* src, int ok) {
    int sz = ok ? 16 : 0;
    asm volatile("cp.async.ca.shared.global [%0], [%1], 16, %2;"
                 :: "r"(dst), "l"(src), "r"(sz));
}
__device__ __forceinline__ void cp_commit() {
    asm volatile("cp.async.commit_group;" ::: "memory");
}
template<int N> __device__ __forceinline__ void cp_wait() {
    asm volatile("cp.async.wait_group %0;" :: "n"(N) : "memory");
}
__device__ __forceinline__ void ldm4(uint32_t* r, uint32_t addr) {
    asm volatile("ldmatrix.sync.aligned.m8n8.x4.shared.b16 {%0,%1,%2,%3}, [%4];"
                 : "=r"(r[0]), "=r"(r[1]), "=r"(r[2]), "=r"(r[3]) : "r"(addr));
}
__device__ __forceinline__ void ldm4t(uint32_t* r, uint32_t addr) {
    asm volatile("ldmatrix.sync.aligned.m8n8.x4.trans.shared.b16 {%0,%1,%2,%3}, [%4];"
                 : "=r"(r[0]), "=r"(r[1]), "=r"(r[2]), "=r"(r[3]) : "r"(addr));
}
__device__ __forceinline__ void ldm2(uint32_t* r, uint32_t addr) {
    asm volatile("ldmatrix.sync.aligned.m8n8.x2.shared.b16 {%0,%1}, [%2];"
                 : "=r"(r[0]), "=r"(r[1]) : "r"(addr));
}
__device__ __forceinline__ void ldm2t(uint32_t* r, uint32_t addr) {
    asm volatile("ldmatrix.sync.aligned.m8n8.x2.trans.shared.b16 {%0,%1}, [%2];"
                 : "=r"(r[0]), "=r"(r[1]) : "r"(addr));
}
__device__ __forceinline__ void sts128(uint32_t a, int4 v) {
    asm volatile("st.shared.v4.b32 [%0], {%1,%2,%3,%4};"
                 :: "r"(a), "r"(v.x), "r"(v.y), "r"(v.z), "r"(v.w));
}
__device__ __forceinline__ void mma16816(float* c, const uint32_t* a,
                                         const uint32_t* b) {
    asm volatile(
        "mma.sync.aligned.m16n8k16.row.col.f32.f16.f16.f32 "
        "{%0,%1,%2,%3}, {%4,%5,%6,%7}, {%8,%9}, {%0,%1,%2,%3};"
        : "+f"(c[0]), "+f"(c[1]), "+f"(c[2]), "+f"(c[3])
        : "r"(a[0]), "r"(a[1]), "r"(a[2]), "r"(a[3]), "r"(b[0]), "r"(b[1]));
}
__device__ __forceinline__ void split_fp16(float v, __half& hi, __half& lo) {
    hi = __float2half_rn(v);
    lo = __float2half_rn(v - __half2float(hi));
}

// ---------------- SMEM geometry ---------------------------------------------
#define TROW 80
#define TILE_B (128 * TROW)          // 10240 B (K-major 128x32 tile)
#define STAGE_B (4 * TILE_B)         // xxt: Ah, Al, Bh, Bl
#define STAGE2_B (2 * TILE_B)        // conv: Ah, Bh
#define DYN_SMEM (2 * STAGE_B)       // 81920 B
#define DYNC_SMEM (3 * STAGE2_B)     // 61440 B (conv, 3-stage)
// ygemm: A = x tile [32 j][128 hw], pitch 272 B; B = att tile K-major (TROW)
#define XROW 272
#define XTILE_B (32 * XROW)          // 8704 B
#define STAGEY_B (XTILE_B + TILE_B)  // 18944 B
#define DYNY_SMEM (2 * STAGEY_B)     // 37888 B
// reduce: W tiles K-major (TROW), F tiles N-major 32k x 128n, 272 B rows
#define FROWB 272
#define FTILE_B (32 * FROWB)         // 8704 B
#define RFOFF_H (2 * TILE_B)         // 20480
#define RFOFF_L (RFOFF_H + FTILE_B)  // 29184
#define RSTAGE_B (2 * TILE_B + 2 * FTILE_B)  // 37888
#define RDYN_SMEM (2 * RSTAGE_B)     // 75776

// contiguous 128x32 K-major tile load via cp.async: 512 chunks / 256 threads
__device__ __forceinline__ void cpa_tile(uint32_t sdst, const __half* g,
                                         size_t stride, int k0, int tid) {
    #pragma unroll
    for (int it = 0; it < 2; it++) {
        int ch = it * 256 + tid;
        int row = ch >> 2, seg = ch & 3;
        cp16(sdst + row * TROW + seg * 16,
             g + (size_t)row * stride + k0 + seg * 8);
    }
}

// one k16 slab: 4 m-atoms x 4 n-atoms of m16n8k16 (A row-major, B K-major)
__device__ __forceinline__ void mma_k16(uint32_t aBase, uint32_t bBase, int kk,
                                        int lane, float c[4][4][4]) {
    uint32_t a[4][4], b[4][2];
    int arow = lane & 15, asel = lane >> 4;
    #pragma unroll
    for (int am = 0; am < 4; am++)
        ldm4(a[am], aBase + (am * 16 + arow) * TROW + (kk + asel * 8) * 2);
    int brow = lane & 7, bsel = (lane >> 3) & 1;
    #pragma unroll
    for (int bn = 0; bn < 4; bn++)
        ldm2(b[bn], bBase + (bn * 8 + brow) * TROW + (kk + bsel * 8) * 2);
    #pragma unroll
    for (int am = 0; am < 4; am++)
        #pragma unroll
        for (int bn = 0; bn < 4; bn++)
            mma16816(c[am][bn], a[am], b[bn]);
}
// one k16 slab with A loaded TRANSPOSED from S[k][m] (pitch XROW)
__device__ __forceinline__ void mma_k16_tA(uint32_t sA, uint32_t sB, int kk,
                                           int wm, int wn, int lane,
                                           float c[4][4][4]) {
    uint32_t a[4][4], b[4][2];
    int g = lane >> 3;
    int krow = kk + ((g >> 1) << 3) + (lane & 7);
    int mcol = ((g & 1) << 3);
    #pragma unroll
    for (int am = 0; am < 4; am++)
        ldm4t(a[am], sA + krow * XROW + (wm + am * 16 + mcol) * 2);
    int brow = lane & 7, bsel = (lane >> 3) & 1;
    #pragma unroll
    for (int bn = 0; bn < 4; bn++)
        ldm2(b[bn], sB + (wn + bn * 8 + brow) * TROW + (kk + bsel * 8) * 2);
    #pragma unroll
    for (int am = 0; am < 4; am++)
        #pragma unroll
        for (int bn = 0; bn < 4; bn++)
            mma16816(c[am][bn], a[am], b[bn]);
}

// FUSED 3-term stage (xxt, K-major B): Bh,Bl,Ah loaded once -> hh + hl,
// then Al -> lh. Per-accumulator order hh,hl,lh (bit-identical to 3-call).
__device__ __forceinline__ void stage_xxt_f(uint32_t sb, int wm, int wn,
                                            int lane, float c[4][4][4]) {
    uint32_t Ah = sb + wm * TROW,              Al = Ah + TILE_B;
    uint32_t Bh = sb + 2 * TILE_B + wn * TROW, Bl = Bh + TILE_B;
    int arow = lane & 15, asel = lane >> 4;
    int brow = lane & 7,  bsel = (lane >> 3) & 1;
    #pragma unroll
    for (int kk = 0; kk < 32; kk += 16) {
        uint32_t bh[4][2], bl[4][2], a[4][4];
        #pragma unroll
        for (int bn = 0; bn < 4; bn++) {
            ldm2(bh[bn], Bh + (bn * 8 + brow) * TROW + (kk + bsel * 8) * 2);
            ldm2(bl[bn], Bl + (bn * 8 + brow) * TROW + (kk + bsel * 8) * 2);
        }
        #pragma unroll
        for (int am = 0; am < 4; am++)
            ldm4(a[am], Ah + (am * 16 + arow) * TROW + (kk + asel * 8) * 2);
        #pragma unroll
        for (int am = 0; am < 4; am++)
            #pragma unroll
            for (int bn = 0; bn < 4; bn++) {
                mma16816(c[am][bn], a[am], bh[bn]);
                mma16816(c[am][bn], a[am], bl[bn]);
            }
        #pragma unroll
        for (int am = 0; am < 4; am++)
            ldm4(a[am], Al + (am * 16 + arow) * TROW + (kk + asel * 8) * 2);
        #pragma unroll
        for (int am = 0; am < 4; am++)
            #pragma unroll
            for (int bn = 0; bn < 4; bn++)
                mma16816(c[am][bn], a[am], bh[bn]);
    }
}
// FUSED 3-term stage (reduce, N-major F via ldm2t): same ordering
__device__ __forceinline__ void stage_reduce_f(uint32_t sb, int wm, int wn,
                                               int lane, float c[4][4][4]) {
    uint32_t Ah = sb + wm * TROW, Al = Ah + TILE_B;
    uint32_t Fh = sb + RFOFF_H + wn * 2, Fl = sb + RFOFF_L + wn * 2;
    int arow = lane & 15, asel = lane >> 4;
    #pragma unroll
    for (int kk = 0; kk < 32; kk += 16) {
        uint32_t bh[4][2], bl[4][2], a[4][4];
        uint32_t frh = Fh + (kk + (lane & 15)) * FROWB;
        uint32_t frl = Fl + (kk + (lane & 15)) * FROWB;
        #pragma unroll
        for (int bn = 0; bn < 4; bn++) {
            ldm2t(bh[bn], frh + bn * 16);
            ldm2t(bl[bn], frl + bn * 16);
        }
        #pragma unroll
        for (int am = 0; am < 4; am++)
            ldm4(a[am], Ah + (am * 16 + arow) * TROW + (kk + asel * 8) * 2);
        #pragma unroll
        for (int am = 0; am < 4; am++)
            #pragma unroll
            for (int bn = 0; bn < 4; bn++) {
                mma16816(c[am][bn], a[am], bh[bn]);
                mma16816(c[am][bn], a[am], bl[bn]);
            }
        #pragma unroll
        for (int am = 0; am < 4; am++)
            ldm4(a[am], Al + (am * 16 + arow) * TROW + (kk + asel * 8) * 2);
        #pragma unroll
        for (int am = 0; am < 4; am++)
            #pragma unroll
            for (int bn = 0; bn < 4; bn++)
                mma16816(c[am][bn], a[am], bh[bn]);
    }
}
// 1-term stage (conv): Ah x Bh
__device__ __forceinline__ void stage_compute_1(uint32_t sb, int wm, int wn,
                                                int lane, float c[4][4][4]) {
    uint32_t Ah = sb + wm * TROW;
    uint32_t Bh = sb + TILE_B + wn * TROW;
    #pragma unroll
    for (int kk = 0; kk < 32; kk += 16) mma_k16(Ah, Bh, kk, lane, c);
}

#define GEMM_VARS()                                                            \
    extern __shared__ __align__(16) char dsm[];                                \
    uint32_t sb0 = smem_u32(dsm);                                              \
    int tid = threadIdx.x, wid = tid >> 5, lane = tid & 31;                    \
    int wm = (wid >> 2) * 64, wn = (wid & 3) * 32;                             \
    float c[4][4][4] = {};

// ---------------- small prep kernels ----------------------------------------
__global__ void prep_bn(const float* __restrict__ rb, const float* __restrict__ rg,
                        const float* __restrict__ rbe, const float* __restrict__ rm,
                        const float* __restrict__ rv,
                        const float* __restrict__ cb, const float* __restrict__ cg,
                        const float* __restrict__ cbe, const float* __restrict__ cm,
                        const float* __restrict__ cv) {
    int i = blockIdx.x * blockDim.x + threadIdx.x;
    if (i < CMID) {
        float inv = rg[i] * rsqrtf(rv[i] + EPS);
        g_scale1[i] = inv;
        g_shift1[i] = (rb[i] - rm[i]) * inv + rbe[i];
        float inv3 = cg[i] * rsqrtf(cv[i] + EPS);
        g_scale3[i] = inv3;
        g_shift3[i] = (cb[i] - cm[i]) * inv3 + cbe[i];
    }
}
// w1 split + zsum zero folded in
__global__ void cvt_w1(const float* __restrict__ w) {
    int i = blockIdx.x * blockDim.x + threadIdx.x;
    __half hi, lo; split_fp16(w[i], hi, lo);
    g_w1_h[i] = hi; g_w1_l[i] = lo;
    if (i < BATCH * CMID) g_zsum[i] = 0.f;
}
__global__ void cvt_w3(const float* __restrict__ w) {
    int i = blockIdx.x * blockDim.x + threadIdx.x;   // over 512*4608
    int o = i / K33, k = i - o * K33;
    int rs = k >> 9, cc = k & 511;
    int r = rs / 3, s = rs - r * 3;
    g_w3_h[i] = __float2half_rn(w[((o * CMID + cc) * 3 + r) * 3 + s]);
}

// ---------------- K1: reduce GEMM (M=512, N=25088, K=2048) + BN/ReLU --------
__global__ __launch_bounds__(256, 2) void k_reduce_mma(const float* __restrict__ f2,
                                                       const float* __restrict__ f3) {
    GEMM_VARS();
    int m0 = blockIdx.x * 128, n0 = blockIdx.y * 128;
    const int T = CIN / 32;    // 64 stages
    const __half* Awh = g_w1_h + (size_t)m0 * CIN;
    const __half* Awl = g_w1_l + (size_t)m0 * CIN;

    int fk = tid >> 3;                      // k row 0..31
    uint32_t fcol = (uint32_t)(tid & 7) * 32u;  // byte col in F tile
    const float* pbase[4];
    #pragma unroll
    for (int q = 0; q < 4; q++) {
        int cg = n0 + (tid & 7) * 16 + q * 4;   // 4-aligned, single batch
        int b = cg / HW, hw = cg - b * HW;
        const float* F = (b < HB) ? f2 + (size_t)b * CIN * HW
                                  : f3 + (size_t)(b - HB) * CIN * HW;
        pbase[q] = F + hw;
    }

    float fr[16];
    #define LDF(kt) {                                                          \
        size_t ko = (size_t)((kt) * 32 + fk) * HW;                             \
        _Pragma("unroll")                                                      \
        for (int q = 0; q < 4; q++)                                            \
            *reinterpret_cast<float4*>(fr + q * 4) =                           \
                *reinterpret_cast<const float4*>(pbase[q] + ko);               \
    }
    #define STSF(s) {                                                          \
        uint32_t ph[8], pl[8];                                                 \
        _Pragma("unroll")                                                      \
        for (int e = 0; e < 8; e++) {                                          \
            __half h0_, l0_, h1_, l1_;                                         \
            split_fp16(fr[2 * e], h0_, l0_);                                   \
            split_fp16(fr[2 * e + 1], h1_, l1_);                               \
            __half2 hh = __halves2half2(h0_, h1_);                             \
            __half2 ll = __halves2half2(l0_, l1_);                             \
            ph[e] = *reinterpret_cast<uint32_t*>(&hh);                         \
            pl[e] = *reinterpret_cast<uint32_t*>(&ll);                         \
        }                                                                      \
        uint32_t fa = (s) + RFOFF_H + (uint32_t)fk * FROWB + fcol;             \
        sts128(fa,      make_int4(ph[0], ph[1], ph[2], ph[3]));                \
        sts128(fa + 16, make_int4(ph[4], ph[5], ph[6], ph[7]));                \
        fa += (RFOFF_L - RFOFF_H);                                             \
        sts128(fa,      make_int4(pl[0], pl[1], pl[2], pl[3]));                \
        sts128(fa + 16, make_int4(pl[4], pl[5], pl[6], pl[7]));                \
    }
    #define ISSUEW(kt) {                                                       \
        uint32_t s = sb0 + ((kt) & 1) * RSTAGE_B; int k0 = (kt) * 32;          \
        cpa_tile(s,          Awh, CIN, k0, tid);                               \
        cpa_tile(s + TILE_B, Awl, CIN, k0, tid);                               \
        cp_commit(); }

    LDF(0);
    ISSUEW(0);
    for (int kt = 0; kt < T; kt++) {
        uint32_t s = sb0 + (kt & 1) * RSTAGE_B;
        STSF(s);
        if (kt + 1 < T) LDF(kt + 1);
        cp_wait<0>();
        __syncthreads();
        if (kt + 1 < T) ISSUEW(kt + 1);
        stage_reduce_f(s, wm, wn, lane, c);
        __syncthreads();
    }
    #undef LDF
    #undef STSF
    #undef ISSUEW
    #pragma unroll
    for (int am = 0; am < 4; am++) {
        #pragma unroll
        for (int half = 0; half < 2; half++) {
            int o = m0 + wm + am * 16 + (lane >> 2) + half * 8;
            float sc = g_scale1[o], sh = g_shift1[o];
            #pragma unroll
            for (int bn = 0; bn < 4; bn++) {
                // col pairs (even, even+1) never cross a batch boundary
                int col = n0 + wn + bn * 8 + 2 * (lane & 3);
                int b = col / HW, hw = col - b * HW;
                float v0 = fmaxf(c[am][bn][half * 2 + 0] * sc + sh, 0.f);
                float v1 = fmaxf(c[am][bn][half * 2 + 1] * sc + sh, 0.f);
                __half h0, l0, h1, l1;
                split_fp16(v0, h0, l0);
                split_fp16(v1, h1, l1);
                size_t i1 = ((size_t)b * CMID + o) * HWP + hw;
                *reinterpret_cast<__half2*>(g_x_h + i1) = __halves2half2(h0, h1);
                *reinterpret_cast<__half2*>(g_x_l + i1) = __halves2half2(l0, l1);
            }
        }
    }
}

// ---------------- K2: XXt per batch, SYMMETRIC: 10 upper-triangle tiles -----
__global__ __launch_bounds__(256, 2) void k_xxt_mma() {
    GEMM_VARS();
    const int TI[10] = {0, 0, 0, 0, 1, 1, 1, 2, 2, 3};
    const int TJ[10] = {0, 1, 2, 3, 1, 2, 3, 2, 3, 3};
    int m0 = TI[blockIdx.x] * 128, n0 = TJ[blockIdx.x] * 128;
    int b = blockIdx.z;
    const __half* Xh = g_x_h + (size_t)b * CMID * HWP;
    const __half* Xl = g_x_l + (size_t)b * CMID * HWP;
    const int T = KXT / 32;    // 7 stages
    #define ISSUE(kt) {                                                        \
        uint32_t s = sb0 + ((kt) & 1) * STAGE_B; int k0 = (kt) * 32;           \
        cpa_tile(s,              Xh + (size_t)m0 * HWP, HWP, k0, tid);         \
        cpa_tile(s + TILE_B,     Xl + (size_t)m0 * HWP, HWP, k0, tid);         \
        cpa_tile(s + 2 * TILE_B, Xh + (size_t)n0 * HWP, HWP, k0, tid);         \
        cpa_tile(s + 3 * TILE_B, Xl + (size_t)n0 * HWP, HWP, k0, tid); }
    ISSUE(0); cp_commit();
    for (int kt = 0; kt < T; kt++) {
        if (kt + 1 < T) { ISSUE(kt + 1); cp_commit(); cp_wait<1>(); }
        else cp_wait<0>();
        __syncthreads();
        stage_xxt_f(sb0 + (kt & 1) * STAGE_B, wm, wn, lane, c);
        __syncthreads();
    }
    #undef ISSUE
    float* out = g_att + (size_t)b * CMID * CMID;
    if (m0 == n0) {
        #pragma unroll
        for (int am = 0; am < 4; am++)
            #pragma unroll
            for (int half = 0; half < 2; half++) {
                int r = m0 + wm + am * 16 + (lane >> 2) + half * 8;
                #pragma unroll
                for (int bn = 0; bn < 4; bn++) {
                    int col = n0 + wn + bn * 8 + 2 * (lane & 3);
                    out[(size_t)r * CMID + col]     = c[am][bn][half * 2 + 0];
                    out[(size_t)r * CMID + col + 1] = c[am][bn][half * 2 + 1];
                }
            }
    } else {
        float* st = reinterpret_cast<float*>(dsm);   // [128][129]
        #pragma unroll
        for (int am = 0; am < 4; am++)
            #pragma unroll
            for (int half = 0; half < 2; half++) {
                int r = wm + am * 16 + (lane >> 2) + half * 8;
                #pragma unroll
                for (int bn = 0; bn < 4; bn++) {
                    int col = wn + bn * 8 + 2 * (lane & 3);
                    st[r * 129 + col]     = c[am][bn][half * 2 + 0];
                    st[r * 129 + col + 1] = c[am][bn][half * 2 + 1];
                }
            }
        __syncthreads();
        for (int idx = tid; idx < 128 * 128; idx += 256) {
            int r = idx >> 7, cl = idx & 127;
            out[(size_t)(m0 + r) * CMID + n0 + cl] = st[r * 129 + cl];
        }
        for (int idx = tid; idx < 128 * 128; idx += 256) {
            int r = idx >> 7, cl = idx & 127;
            out[(size_t)(n0 + r) * CMID + m0 + cl] = st[cl * 129 + r];
        }
    }
}

// ---------------- K3: softmax(-S) rowwise -> fp16, vectorized ----------------
__global__ __launch_bounds__(256) void k_softmax() {
    int gw = (blockIdx.x * blockDim.x + threadIdx.x) >> 5;
    int lane = threadIdx.x & 31;
    if (gw >= BATCH * CMID) return;
    const float* row = g_att + (size_t)gw * CMID + lane * 16;
    float v[16];
    #pragma unroll
    for (int q = 0; q < 4; q++)
        *reinterpret_cast<float4*>(v + q * 4) =
            *reinterpret_cast<const float4*>(row + q * 4);
    float mn = v[0];
    #pragma unroll
    for (int t = 1; t < 16; t++) mn = fminf(mn, v[t]);
    #pragma unroll
    for (int o = 16; o; o >>= 1) mn = fminf(mn, __shfl_xor_sync(~0u, mn, o));
    float e[16], sum = 0.f;
    #pragma unroll
    for (int t = 0; t < 16; t++) { e[t] = __expf(mn - v[t]); sum += e[t]; }
    #pragma unroll
    for (int o = 16; o; o >>= 1) sum += __shfl_xor_sync(~0u, sum, o);
    float inv = 1.f / sum;
    __half hb[16];
    #pragma unroll
    for (int t = 0; t < 16; t++) hb[t] = __float2half_rn(e[t] * inv);
    __half* dst = g_att_h + (size_t)gw * CMID + lane * 16;
    *reinterpret_cast<int4*>(dst)     = *reinterpret_cast<int4*>(hb);
    *reinterpret_cast<int4*>(dst + 8) = *reinterpret_cast<int4*>(hb + 8);
}

// ---------------- K4: yT = Xt @ attT (M=hw 196pad256, N=i 512, K=j 512) -----
__global__ __launch_bounds__(256, 2) void k_ygemm_mma() {
    GEMM_VARS();
    int hw0 = blockIdx.x * 128, n0 = blockIdx.y * 128, b = blockIdx.z;
    const __half* Xh = g_x_h + (size_t)b * CMID * HWP + hw0;
    const __half* At = g_att_h + ((size_t)b * CMID + n0) * CMID;
    const int T = CMID / 32;   // 16 stages over j
    #define ISSUE(kt) {                                                        \
        uint32_t s = sb0 + ((kt) & 1) * STAGEY_B; int k0 = (kt) * 32;          \
        _Pragma("unroll")                                                      \
        for (int it = 0; it < 2; it++) {                                       \
            int ch = it * 256 + tid;                                           \
            int row = ch >> 4, seg = ch & 15;                                  \
            cp16(s + row * XROW + seg * 16,                                    \
                 Xh + (size_t)(k0 + row) * HWP + seg * 8);                     \
        }                                                                      \
        cpa_tile(s + XTILE_B, At, CMID, k0, tid); }
    ISSUE(0); cp_commit();
    for (int kt = 0; kt < T; kt++) {
        if (kt + 1 < T) { ISSUE(kt + 1); cp_commit(); cp_wait<1>(); }
        else cp_wait<0>();
        __syncthreads();
        uint32_t s = sb0 + (kt & 1) * STAGEY_B;
        #pragma unroll
        for (int kk = 0; kk < 32; kk += 16)
            mma_k16_tA(s, s + XTILE_B, kk, wm, wn, lane, c);
        __syncthreads();
    }
    #undef ISSUE
    #pragma unroll
    for (int am = 0; am < 4; am++)
        #pragma unroll
        for (int half = 0; half < 2; half++) {
            int hw = hw0 + wm + am * 16 + (lane >> 2) + half * 8;
            if (hw < HW) {
                __half* dst = g_yT_h + ((size_t)b * HW + hw) * CMID + n0;
                #pragma unroll
                for (int bn = 0; bn < 4; bn++) {
                    int i = wn + bn * 8 + 2 * (lane & 3);
                    __half2 p;
                    p.x = __float2half_rn(c[am][bn][half * 2 + 0]);
                    p.y = __float2half_rn(c[am][bn][half * 2 + 1]);
                    *reinterpret_cast<__half2*>(dst + i) = p;
                }
            }
        }
}

// ---------------- K5: conv3 implicit GEMM (M=512, N=25088, K=4608), 1-term --
__global__ __launch_bounds__(256, 2) void k_conv_mma() {
    GEMM_VARS();
    int m0 = blockIdx.x * 128, n0 = blockIdx.y * 128;
    const int T = K33 / 32;    // 144 stages
    int gr[2], gb[2], gph[2], gpw[2];
    #pragma unroll
    for (int it = 0; it < 2; it++) {
        int row = it * 64 + (tid >> 2);
        gr[it] = row;
        int col = n0 + row;
        gb[it] = col / HW;
        int p = col - gb[it] * HW;
        gph[it] = p / 14; gpw[it] = p - gph[it] * 14;
    }
    int seg = tid & 3;
    #define ISSUE(kt) {                                                        \
        uint32_t s = sb0 + ((kt) % 3) * STAGE2_B; int k0 = (kt) * 32;          \
        cpa_tile(s, g_w3_h + (size_t)m0 * K33, K33, k0, tid);                  \
        int rs = (kt) >> 4, c0 = ((kt) & 15) * 32;                             \
        int dr = rs / 3 - 1, ds = rs - (rs / 3) * 3 - 1;                       \
        _Pragma("unroll")                                                      \
        for (int it = 0; it < 2; it++) {                                       \
            int ih = gph[it] + dr, iw = gpw[it] + ds;                          \
            int ok = ((unsigned)ih < 14u) && ((unsigned)iw < 14u);             \
            size_t pix = (size_t)gb[it] * HW + (ok ? ih * 14 + iw : 0);        \
            size_t gidx = pix * CMID + c0 + seg * 8;                           \
            cp16z(s + TILE_B + gr[it] * TROW + seg * 16, g_yT_h + gidx, ok);   \
        } }
    ISSUE(0); cp_commit();
    ISSUE(1); cp_commit();
    for (int kt = 0; kt < T; kt++) {
        if (kt + 2 < T) { ISSUE(kt + 2); cp_commit(); cp_wait<2>(); }
        else if (kt + 1 < T) cp_wait<1>();
        else cp_wait<0>();
        __syncthreads();
        stage_compute_1(sb0 + (kt % 3) * STAGE2_B, wm, wn, lane, c);
        __syncthreads();
    }
    #undef ISSUE
    int b0 = n0 / HW;
    int split = (b0 + 1) * HW - n0;   // local cols < split belong to b0
    #pragma unroll
    for (int am = 0; am < 4; am++)
        #pragma unroll
        for (int half = 0; half < 2; half++) {
            int o = m0 + wm + am * 16 + (lane >> 2) + half * 8;
            float sc = g_scale3[o], sh = g_shift3[o];
            float s0 = 0.f, s1 = 0.f;
            #pragma unroll
            for (int bn = 0; bn < 4; bn++)
                #pragma unroll
                for (int e = 0; e < 2; e++) {
                    float v = fmaxf(c[am][bn][half * 2 + e] * sc + sh, 0.f);
                    int lcol = wn + bn * 8 + 2 * (lane & 3) + e;
                    if (lcol < split) s0 += v; else s1 += v;
                }
            s0 += __shfl_xor_sync(~0u, s0, 1);
            s0 += __shfl_xor_sync(~0u, s0, 2);
            s1 += __shfl_xor_sync(~0u, s1, 1);
            s1 += __shfl_xor_sync(~0u, s1, 2);
            if ((lane & 3) == 0) {
                atomicAdd(&g_zsum[b0 * CMID + o], s0 * (1.f / HW));
                if (split < 128)
                    atomicAdd(&g_zsum[(b0 + 1) * CMID + o], s1 * (1.f / HW));
            }
        }
}

// ---------------- K7: fc1 + ReLU --------------------------------------------
__global__ __launch_bounds__(256) void k_fc1(const float* __restrict__ w,
                                             const float* __restrict__ bias) {
    int gw = (blockIdx.x * blockDim.x + threadIdx.x) >> 5;
    int lane = threadIdx.x & 31;
    if (gw >= BATCH * 200) return;
    int b = gw / 200, j = gw - b * 200;
    const float* zr = g_zsum + b * CMID;
    const float* wr = w + (size_t)j * CMID;
    float s = 0.f;
    for (int k = lane; k < CMID; k += 32) s += zr[k] * wr[k];
    #pragma unroll
    for (int o = 16; o; o >>= 1) s += __shfl_xor_sync(~0u, s, o);
    if (lane == 0) g_h[gw] = fmaxf(s + bias[j], 0.f);
}

// ---------------- K8: fc2 + branch-sum --------------------------------------
__global__ __launch_bounds__(256) void k_fc2(const float* __restrict__ w,
                                             const float* __restrict__ bias,
                                             float* __restrict__ out) {
    int gw = (blockIdx.x * blockDim.x + threadIdx.x) >> 5;
    int lane = threadIdx.x & 31;
    if (gw >= HB * 200) return;
    int b = gw / 200, j = gw - b * 200;
    const float* h1 = g_h + (size_t)b * 200;
    const float* h2 = g_h + (size_t)(b + HB) * 200;
    const float* wr = w + (size_t)j * 200;
    float s = 0.f;
    for (int k = lane; k < 200; k += 32) s += (h1[k] + h2[k]) * wr[k];
    #pragma unroll
    for (int o = 16; o; o >>= 1) s += __shfl_xor_sync(~0u, s, o);
    if (lane == 0) out[gw] = s + 2.f * bias[j];
}

// ---------------- launch ----------------------------------------------------
extern "C" void kernel_launch(void* const* d_in, const int* in_sizes, int n_in,
                              void* d_out, int out_size) {
    const float* f2  = (const float*)d_in[0];
    const float* f3  = (const float*)d_in[1];
    const float* rw  = (const float*)d_in[2];
    const float* rb  = (const float*)d_in[3];
    const float* rg  = (const float*)d_in[4];
    const float* rbe = (const float*)d_in[5];
    const float* rm  = (const float*)d_in[6];
    const float* rv  = (const float*)d_in[7];
    const float* c3w = (const float*)d_in[8];
    const float* c3b = (const float*)d_in[9];
    const float* c3g = (const float*)d_in[10];
    const float* c3be= (const float*)d_in[11];
    const float* c3m = (const float*)d_in[12];
    const float* c3v = (const float*)d_in[13];
    const float* f1w = (const float*)d_in[14];
    const float* f1b = (const float*)d_in[15];
    const float* f2w = (const float*)d_in[16];
    const float* f2b = (const float*)d_in[17];
    float* out = (float*)d_out;

    cudaFuncSetAttribute(k_reduce_mma, cudaFuncAttributeMaxDynamicSharedMemorySize, RDYN_SMEM);
    cudaFuncSetAttribute(k_xxt_mma,    cudaFuncAttributeMaxDynamicSharedMemorySize, DYN_SMEM);
    cudaFuncSetAttribute(k_ygemm_mma,  cudaFuncAttributeMaxDynamicSharedMemorySize, DYNY_SMEM);
    cudaFuncSetAttribute(k_conv_mma,   cudaFuncAttributeMaxDynamicSharedMemorySize, DYNC_SMEM);

    prep_bn<<<2, 256>>>(rb, rg, rbe, rm, rv, c3b, c3g, c3be, c3m, c3v);
    cvt_w1<<<(CMID * CIN) / 256, 256>>>(rw);
    cvt_w3<<<(CMID * K33) / 256, 256>>>(c3w);

    k_reduce_mma<<<dim3(4, NFLAT / 128), 256, RDYN_SMEM>>>(f2, f3);
    k_xxt_mma<<<dim3(10, 1, BATCH), 256, DYN_SMEM>>>();
    k_softmax<<<(BATCH * CMID) / 8, 256>>>();
    k_ygemm_mma<<<dim3(2, 4, BATCH), 256, DYNY_SMEM>>>();
    k_conv_mma<<<dim3(4, NFLAT / 128), 256, DYNC_SMEM>>>();
    k_fc1<<<(BATCH * 200 + 7) / 8, 256>>>(f1w, f1b);
    k_fc2<<<(HB * 200 + 7) / 8, 256>>>(f2w, f2b, out);
}